// round 14
// baseline (speedup 1.0000x reference)
#include <cuda_runtime.h>
#include <cuda_bf16.h>
#include <cstdint>

// Problem constants
#define Bq   4
#define Sq   2048
#define Dq   512
#define Hq   8
#define LN_EPS 1e-5f

// attn smem layout (bytes)
#define SST        2052
#define VSTG2      17408                      // V stage: 64 d-rows x 272B (128 keys)
#define OFF_R      (16 * SST * 4)             // 131,328 (scores / V ring / red)
#define KSTG_BYTES 34816                      // K stage: 128 keys x 272B
#define OFF_Q      (OFF_R + 2 * KSTG_BYTES)   // 200,960 (Q stage)
#define SMEM_ATTN  (OFF_Q + 4352)             // 205,312
#define PBS        2056
#define NTK        16
#define NTV        16

// Scratch (device globals)
__device__ __align__(16) uint16_t g_Q[(size_t)Bq*Hq*Sq*128];   // bf16 [B,H,S,(hi64|lo64)]
__device__ __align__(16) uint16_t g_K[(size_t)Bq*Hq*Sq*128];
__device__ __align__(16) uint16_t g_V[(size_t)Bq*Hq*64*Sq];    // bf16 transposed [B,H,d,S]
__device__ float    g_pre[(size_t)Bq*Sq*Dq];
// bf16 hi/lo splits
__device__ __align__(16) uint16_t s_Qh[(size_t)Bq*Sq*Dq], s_Ql[(size_t)Bq*Sq*Dq];
__device__ __align__(16) uint16_t s_Kh[(size_t)Bq*Sq*Dq], s_Kl[(size_t)Bq*Sq*Dq];
__device__ __align__(16) uint16_t s_Vh[(size_t)Bq*Sq*Dq], s_Vl[(size_t)Bq*Sq*Dq];
__device__ __align__(16) uint16_t s_Ch[(size_t)Bq*Sq*Dq], s_Cl[(size_t)Bq*Sq*Dq];
__device__ __align__(16) uint16_t w_Qh[512*512], w_Ql[512*512];
__device__ __align__(16) uint16_t w_Kh[512*512], w_Kl[512*512];
__device__ __align__(16) uint16_t w_Vh[512*512], w_Vl[512*512];
__device__ __align__(16) uint16_t w_Fh[512*512], w_Fl[512*512];

// ---------------------------------------------------------------------------
__device__ __forceinline__ uint16_t bfbits(float x) {
    __nv_bfloat16 b = __float2bfloat16_rn(x);
    return *(uint16_t*)&b;
}
__device__ __forceinline__ float bf2f(uint16_t u) {
    __nv_bfloat16 b = *(__nv_bfloat16*)&u;
    return __bfloat162float(b);
}

__device__ __forceinline__ void mma16(float* c, const uint32_t* a, uint32_t b0, uint32_t b1) {
    asm volatile(
        "mma.sync.aligned.m16n8k16.row.col.f32.bf16.bf16.f32 "
        "{%0,%1,%2,%3}, {%4,%5,%6,%7}, {%8,%9}, {%0,%1,%2,%3};"
        : "+f"(c[0]), "+f"(c[1]), "+f"(c[2]), "+f"(c[3])
        : "r"(a[0]), "r"(a[1]), "r"(a[2]), "r"(a[3]), "r"(b0), "r"(b1));
}

__device__ __forceinline__ void cp16g(void* dst, const void* src) {
    uint32_t d = (uint32_t)__cvta_generic_to_shared(dst);
    asm volatile("cp.async.cg.shared.global [%0], [%1], 16;" :: "r"(d), "l"(src));
}
__device__ __forceinline__ void cp_commit() { asm volatile("cp.async.commit_group;"); }
template<int N> __device__ __forceinline__ void cp_wait() {
    asm volatile("cp.async.wait_group %0;" :: "n"(N));
}

// ---------------------------------------------------------------------------
// Split kernels (proven)
// ---------------------------------------------------------------------------
__global__ __launch_bounds__(512)
void split_in3(const float4* __restrict__ xQ, const float4* __restrict__ xK,
               const float4* __restrict__ xV,
               uint2* __restrict__ hQ, uint2* __restrict__ lQ,
               uint2* __restrict__ hK, uint2* __restrict__ lK,
               uint2* __restrict__ hV, uint2* __restrict__ lV, int n4)
{
    int i = blockIdx.x * 512 + threadIdx.x;
    if (i >= n4) return;
    const int y = blockIdx.y;
    const float4* x = (y == 0) ? xQ : (y == 1) ? xK : xV;
    uint2* hi = (y == 0) ? hQ : (y == 1) ? hK : hV;
    uint2* lo = (y == 0) ? lQ : (y == 1) ? lK : lV;
    float4 v = x[i];
    float vv[4] = {v.x, v.y, v.z, v.w};
    uint16_t h[4], l[4];
#pragma unroll
    for (int k = 0; k < 4; k++) {
        h[k] = bfbits(vv[k]);
        l[k] = bfbits(vv[k] - bf2f(h[k]));
    }
    hi[i] = *(uint2*)h;
    lo[i] = *(uint2*)l;
}

__global__ __launch_bounds__(256)
void splitW4(const float* __restrict__ W0, const float* __restrict__ W1,
             const float* __restrict__ W2, const float* __restrict__ W3,
             uint16_t* __restrict__ h0, uint16_t* __restrict__ l0,
             uint16_t* __restrict__ h1, uint16_t* __restrict__ l1,
             uint16_t* __restrict__ h2, uint16_t* __restrict__ l2,
             uint16_t* __restrict__ h3, uint16_t* __restrict__ l3)
{
    __shared__ float tile[32][33];
    const int z = blockIdx.z;
    const float* W = (z == 0) ? W0 : (z == 1) ? W1 : (z == 2) ? W2 : W3;
    uint16_t* th = (z == 0) ? h0 : (z == 1) ? h1 : (z == 2) ? h2 : h3;
    uint16_t* tl = (z == 0) ? l0 : (z == 1) ? l1 : (z == 2) ? l2 : l3;
    const int bx = blockIdx.x;
    const int by = blockIdx.y;
    const int x = threadIdx.x, y = threadIdx.y;
#pragma unroll
    for (int i = 0; i < 32; i += 8)
        tile[y + i][x] = W[(size_t)(by * 32 + y + i) * 512 + bx * 32 + x];
    __syncthreads();
#pragma unroll
    for (int i = 0; i < 32; i += 8) {
        float v = tile[x][y + i];
        uint16_t hb = bfbits(v);
        size_t o = (size_t)(bx * 32 + y + i) * 512 + by * 32 + x;
        th[o] = hb;
        tl[o] = bfbits(v - bf2f(hb));
    }
}

// ---------------------------------------------------------------------------
// PROVEN 4-term bf16 mainloop as a device function.
// ---------------------------------------------------------------------------
__device__ __forceinline__ void gemm4t_mainloop(
    uint16_t* sb,
    const uint16_t* __restrict__ Ah, const uint16_t* __restrict__ Al,
    const uint16_t* __restrict__ Bh, const uint16_t* __restrict__ Bl,
    int m0, int n0, int tid, int wm, int wn, int g, int t,
    float acc[2][4][4])
{
    const int AU = 128 * 40, BU = 64 * 40;
    const int BUF = 2 * AU + 2 * BU;

#define QK_STAGE(buf, kk_)                                                      \
    {                                                                           \
        uint16_t* _Ash = sb + (buf) * BUF;                                      \
        uint16_t* _Asl = _Ash + AU;                                             \
        uint16_t* _Bsh = _Ash + 2 * AU;                                         \
        uint16_t* _Bsl = _Bsh + BU;                                             \
        const int _k0 = (kk_) * 32;                                             \
        _Pragma("unroll")                                                       \
        for (int _j = 0; _j < 2; _j++) {                                        \
            int _c = tid + _j * 256, _r = _c >> 2, _q = _c & 3;                 \
            cp16g(_Ash + _r * 40 + _q * 8, Ah + (size_t)(m0 + _r) * 512 + _k0 + _q * 8); \
            cp16g(_Asl + _r * 40 + _q * 8, Al + (size_t)(m0 + _r) * 512 + _k0 + _q * 8); \
        }                                                                       \
        {                                                                       \
            int _r = tid >> 2, _q = tid & 3;                                    \
            cp16g(_Bsh + _r * 40 + _q * 8, Bh + (size_t)(n0 + _r) * 512 + _k0 + _q * 8); \
            cp16g(_Bsl + _r * 40 + _q * 8, Bl + (size_t)(n0 + _r) * 512 + _k0 + _q * 8); \
        }                                                                       \
    }

    QK_STAGE(0, 0);
    cp_commit();

#pragma unroll 1
    for (int kk = 0; kk < 16; kk++) {
        cp_wait<0>();
        __syncthreads();
        if (kk < 15) { QK_STAGE((kk + 1) & 1, kk + 1); }
        cp_commit();

        const uint16_t* Ash = sb + (kk & 1) * BUF;
        const uint16_t* Asl = Ash + AU;
        const uint16_t* Bsh = Ash + 2 * AU;
        const uint16_t* Bsl = Bsh + BU;

#pragma unroll
        for (int kc = 0; kc < 2; kc++) {
            uint32_t ah_[2][4], al_[2][4];
#pragma unroll
            for (int mi = 0; mi < 2; mi++) {
                int base = (wm * 32 + mi * 16 + g) * 40 + kc * 16 + 2 * t;
                ah_[mi][0] = *(const uint32_t*)&Ash[base];
                ah_[mi][1] = *(const uint32_t*)&Ash[base + 320];
                ah_[mi][2] = *(const uint32_t*)&Ash[base + 8];
                ah_[mi][3] = *(const uint32_t*)&Ash[base + 328];
                al_[mi][0] = *(const uint32_t*)&Asl[base];
                al_[mi][1] = *(const uint32_t*)&Asl[base + 320];
                al_[mi][2] = *(const uint32_t*)&Asl[base + 8];
                al_[mi][3] = *(const uint32_t*)&Asl[base + 328];
            }
#pragma unroll
            for (int nj = 0; nj < 4; nj++) {
                int nb = (wn * 32 + nj * 8 + g) * 40 + kc * 16 + 2 * t;
                uint32_t bh0 = *(const uint32_t*)&Bsh[nb];
                uint32_t bh1 = *(const uint32_t*)&Bsh[nb + 8];
                uint32_t bl0 = *(const uint32_t*)&Bsl[nb];
                uint32_t bl1 = *(const uint32_t*)&Bsl[nb + 8];
#pragma unroll
                for (int mi = 0; mi < 2; mi++) {
                    mma16(acc[mi][nj], ah_[mi], bh0, bh1);
                    mma16(acc[mi][nj], al_[mi], bh0, bh1);
                    mma16(acc[mi][nj], ah_[mi], bl0, bl1);
                    mma16(acc[mi][nj], al_[mi], bl0, bl1);
                }
            }
        }
    }
#undef QK_STAGE
}

// ---------------------------------------------------------------------------
// Merged Q/K/V projection GEMM (proven).
// ---------------------------------------------------------------------------
__global__ __launch_bounds__(256)
void gemm_qkv(const uint16_t* __restrict__ Qh, const uint16_t* __restrict__ Ql_,
              const uint16_t* __restrict__ WQh, const uint16_t* __restrict__ WQl,
              uint16_t* __restrict__ outQ,
              const uint16_t* __restrict__ Kh, const uint16_t* __restrict__ Kl_,
              const uint16_t* __restrict__ WKh, const uint16_t* __restrict__ WKl,
              uint16_t* __restrict__ outK,
              const uint16_t* __restrict__ Vh, const uint16_t* __restrict__ Vl_,
              const uint16_t* __restrict__ WVh, const uint16_t* __restrict__ WVl,
              uint16_t* __restrict__ outV)
{
    extern __shared__ uint16_t sb[];
    const int z = blockIdx.z;
    const uint16_t* Ah = (z == 0) ? Qh : (z == 1) ? Kh : Vh;
    const uint16_t* Al = (z == 0) ? Ql_ : (z == 1) ? Kl_ : Vl_;
    const uint16_t* Bh = (z == 0) ? WQh : (z == 1) ? WKh : WVh;
    const uint16_t* Bl = (z == 0) ? WQl : (z == 1) ? WKl : WVl;
    uint16_t* out      = (z == 0) ? outQ : (z == 1) ? outK : outV;
    const float scale  = (z == 0) ? 0.125f : 1.0f;

    const int tid = threadIdx.x;
    const int warp = tid >> 5, lane = tid & 31;
    const int g = lane >> 2, t = lane & 3;
    const int wm = warp >> 1, wn = warp & 1;
    const int h  = blockIdx.x;
    const int n0 = h * 64;
    const int m0 = blockIdx.y * 128;

    float acc[2][4][4];
#pragma unroll
    for (int i = 0; i < 2; i++)
#pragma unroll
        for (int j = 0; j < 4; j++)
#pragma unroll
            for (int r = 0; r < 4; r++) acc[i][j][r] = 0.f;

    gemm4t_mainloop(sb, Ah, Al, Bh, Bl, m0, n0, tid, wm, wn, g, t, acc);

    if (z < 2) {
#pragma unroll
        for (int mi = 0; mi < 2; mi++)
#pragma unroll
            for (int nj = 0; nj < 4; nj++) {
                int e = wn * 32 + nj * 8 + 2 * t;
#pragma unroll
                for (int half = 0; half < 2; half++) {
                    int m = m0 + wm * 32 + mi * 16 + g + half * 8;
                    int b = m >> 11, s = m & 2047;
                    size_t base = (((size_t)b * Hq + h) * Sq + s) * 128 + e;
                    float v0 = acc[mi][nj][half * 2]     * scale;
                    float v1 = acc[mi][nj][half * 2 + 1] * scale;
                    uint16_t h0 = bfbits(v0), h1 = bfbits(v1);
                    uint16_t l0 = bfbits(v0 - bf2f(h0)), l1 = bfbits(v1 - bf2f(h1));
                    *(uint32_t*)(out + base)      = (uint32_t)h0 | ((uint32_t)h1 << 16);
                    *(uint32_t*)(out + base + 64) = (uint32_t)l0 | ((uint32_t)l1 << 16);
                }
            }
    } else {
        const int b  = m0 >> 11;
        const size_t hb64 = (size_t)(b * Hq + h) * 64;
#pragma unroll
        for (int mi = 0; mi < 2; mi++)
#pragma unroll
            for (int nj = 0; nj < 4; nj++) {
#pragma unroll
                for (int r = 0; r < 4; r++) {
                    int m = m0 + wm * 32 + mi * 16 + g + (r >> 1) * 8;
                    int d = wn * 32 + nj * 8 + 2 * t + (r & 1);
                    int s = m & 2047;
                    out[(hb64 + d) * Sq + s] = bfbits(acc[mi][nj][r]);
                }
            }
    }
}

// fc GEMM (proven)
__global__ __launch_bounds__(256)
void gemm_fc(const uint16_t* __restrict__ Ah, const uint16_t* __restrict__ Al,
             const uint16_t* __restrict__ Bh, const uint16_t* __restrict__ Bl,
             float* __restrict__ out, const float* __restrict__ resid)
{
    extern __shared__ uint16_t sb[];
    const int tid = threadIdx.x;
    const int warp = tid >> 5, lane = tid & 31;
    const int g = lane >> 2, t = lane & 3;
    const int wm = warp >> 1, wn = warp & 1;
    const int n0 = blockIdx.x * 64;
    const int m0 = blockIdx.y * 128;

    float acc[2][4][4];
#pragma unroll
    for (int i = 0; i < 2; i++)
#pragma unroll
        for (int j = 0; j < 4; j++)
#pragma unroll
            for (int r = 0; r < 4; r++) acc[i][j][r] = 0.f;

    gemm4t_mainloop(sb, Ah, Al, Bh, Bl, m0, n0, tid, wm, wn, g, t, acc);

#pragma unroll
    for (int mi = 0; mi < 2; mi++)
#pragma unroll
        for (int nj = 0; nj < 4; nj++) {
            int n = n0 + wn * 32 + nj * 8 + 2 * t;
#pragma unroll
            for (int half = 0; half < 2; half++) {
                int m = m0 + wm * 32 + mi * 16 + g + half * 8;
                float2 rv = *(const float2*)&resid[(size_t)m * 512 + n];
                *(float2*)&out[(size_t)m * 512 + n] =
                    make_float2(acc[mi][nj][half * 2] + rv.x,
                                acc[mi][nj][half * 2 + 1] + rv.y);
            }
        }
}

// ---------------------------------------------------------------------------
// Fused attention. Phase 2 proven; phase 5 now uses a 4-buffer V ring living
// in the (dead after pass 2) scores region with wait<2> -> 3 iterations of
// staging cover. Streaming hints on mask loads / attn stores.
// ---------------------------------------------------------------------------
__global__ __launch_bounds__(512, 1)
void attn_kernel(const uint16_t* __restrict__ Qm, const uint16_t* __restrict__ Km,
                 const uint16_t* __restrict__ Vt, const unsigned* __restrict__ mask,
                 float* __restrict__ attn_out,
                 uint16_t* __restrict__ ctxh, uint16_t* __restrict__ ctxl)
{
    extern __shared__ char smc[];
    float*    scores = (float*)smc;              // phase2/3 scores; phase5 V ring
    char*     Rb     = smc + OFF_R;              // K double buffer / pb
    uint16_t* pb     = (uint16_t*)Rb;
    uint16_t* qs     = (uint16_t*)(smc + OFF_Q); // Q stage (prologue only)

    const int bh  = blockIdx.x;
    const int qt  = blockIdx.y;
    const int b   = bh >> 3;
    const int h   = bh & 7;
    const int tid = threadIdx.x;
    const int warp = tid >> 5;
    const int lane = tid & 31;
    const int g = lane >> 2;
    const int t = lane & 3;
    const int wg = warp >> 3;
    const int wi = warp & 7;

    const uint16_t* KB = Km + (size_t)bh * Sq * 128;
    const uint16_t* VB = Vt + (size_t)bh * 64 * Sq;

#define STAGE_K(stg, kt_)                                                  \
    {                                                                      \
        char* _d = Rb + (stg) * KSTG_BYTES;                                \
        const uint16_t* _s = KB + (size_t)(kt_) * 128 * 128;               \
        _Pragma("unroll")                                                  \
        for (int _j = 0; _j < 4; _j++) {                                   \
            int _c = tid + _j * 512;                                       \
            int _r = _c >> 4, _c16 = _c & 15;                              \
            cp16g(_d + _r * 272 + _c16 * 16, _s + _r * 128 + _c16 * 8);    \
        }                                                                  \
    }
// V tile in the scores-region ring: 64 d-rows x 272B (128 keys + pad)
#define STAGE_V(stg, kt_)                                                  \
    {                                                                      \
        char* _d = smc + (stg) * VSTG2;                                    \
        const uint16_t* _s = VB + (size_t)(kt_) * 128;                     \
        _Pragma("unroll")                                                  \
        for (int _j = 0; _j < 2; _j++) {                                   \
            int _i = tid + _j * 512;                                       \
            int _dd = _i >> 4, _c = _i & 15;                               \
            cp16g(_d + _dd * 272 + _c * 16, _s + (size_t)_dd * Sq + _c * 8);\
        }                                                                  \
    }

    // prologue: K tile 0 -> buf1 (so tile15 lands in buf0), Q -> OFF_Q
    STAGE_K(1, 0);
    cp_commit();
    if (tid < 256) {
        int r = tid >> 4, c16 = tid & 15;
        cp16g((char*)qs + r * 272 + c16 * 16,
              Qm + (size_t)bh * Sq * 128 + (size_t)(qt * 16 + r) * 128 + c16 * 8);
    }
    cp_commit();
    cp_wait<0>();
    __syncthreads();

    uint32_t qh[4][4], ql[4][4];
#pragma unroll
    for (int ch = 0; ch < 4; ch++) {
        int c0 = ch * 16 + 2 * t;
        qh[ch][0] = *(uint32_t*)&qs[g * 136 + c0];
        qh[ch][1] = *(uint32_t*)&qs[(g + 8) * 136 + c0];
        qh[ch][2] = *(uint32_t*)&qs[g * 136 + c0 + 8];
        qh[ch][3] = *(uint32_t*)&qs[(g + 8) * 136 + c0 + 8];
        ql[ch][0] = *(uint32_t*)&qs[g * 136 + c0 + 64];
        ql[ch][1] = *(uint32_t*)&qs[(g + 8) * 136 + c0 + 64];
        ql[ch][2] = *(uint32_t*)&qs[g * 136 + c0 + 72];
        ql[ch][3] = *(uint32_t*)&qs[(g + 8) * 136 + c0 + 72];
    }

    // ---- phase 2: scores = Q @ K^T ----
    const int n0 = warp * 8;
#pragma unroll 1
    for (int kt = 0; kt < NTK; kt++) {
        if (kt + 1 < NTK) { STAGE_K(kt & 1, kt + 1); cp_commit(); }

        const uint16_t* kb_ = (const uint16_t*)(Rb + ((kt & 1) ^ 1) * KSTG_BYTES);
        float acc[2][4] = {{0.f,0.f,0.f,0.f},{0.f,0.f,0.f,0.f}};
#pragma unroll
        for (int ch = 0; ch < 4; ch++) {
            const uint16_t* kr = &kb_[(n0 + g) * 136 + ch * 16 + 2 * t];
            uint32_t bh0 = *(const uint32_t*)kr;
            uint32_t bh1 = *(const uint32_t*)(kr + 8);
            uint32_t bl0 = *(const uint32_t*)(kr + 64);
            uint32_t bl1 = *(const uint32_t*)(kr + 72);
            mma16(acc[ch & 1], qh[ch], bh0, bh1);
            mma16(acc[ch & 1], ql[ch], bh0, bh1);
            mma16(acc[ch & 1], qh[ch], bl0, bl1);
        }
        int col = kt * 128 + n0 + 2 * t;
        *(float2*)&scores[g * SST + col]       = make_float2(acc[0][0] + acc[1][0], acc[0][1] + acc[1][1]);
        *(float2*)&scores[(g + 8) * SST + col] = make_float2(acc[0][2] + acc[1][2], acc[0][3] + acc[1][3]);

        if (kt + 1 < NTK) { cp_wait<0>(); __syncthreads(); }
    }
    __syncthreads();   // all phase-2 done; scores visible; pb region free

    // ---- phase 3/4: mask+exp+sum, then normalize + attn write + bf16 P pack ----
    {
        const int row = warp;
        const int qg  = qt * 16 + row;
        const uint2* mrow2 = (const uint2*)(mask + ((size_t)b * Sq + qg) * Sq);
        float2* srow2 = (float2*)(scores + row * SST);

        float sum = 0.f;
#pragma unroll 4
        for (int i = lane; i < 1024; i += 32) {
            float2 s = srow2[i];
            uint2  m = __ldcs(&mrow2[i]);
            float px = m.x ? 0.f : __expf(s.x);
            float py = m.y ? 0.f : __expf(s.y);
            srow2[i] = make_float2(px, py);
            sum += px + py;
        }
#pragma unroll
        for (int o = 16; o; o >>= 1) sum += __shfl_xor_sync(0xffffffffu, sum, o);
        float inv = 1.0f / sum;

        uint32_t* prow = (uint32_t*)&pb[row * PBS];
        if (attn_out) {
            float2* arow2 = (float2*)(attn_out + ((size_t)bh * Sq + qg) * Sq);
#pragma unroll 4
            for (int i = lane; i < 1024; i += 32) {
                float2 p = srow2[i];
                float2 pn = make_float2(p.x * inv, p.y * inv);
                __stcs(&arow2[i], pn);
                __nv_bfloat162 h2 = __float22bfloat162_rn(pn);
                prow[i] = *(uint32_t*)&h2;
            }
        } else {
#pragma unroll 4
            for (int i = lane; i < 1024; i += 32) {
                float2 p = srow2[i];
                float2 pn = make_float2(p.x * inv, p.y * inv);
                __nv_bfloat162 h2 = __float22bfloat162_rn(pn);
                prow[i] = *(uint32_t*)&h2;
            }
        }
    }
    __syncthreads();   // pass 2 done everywhere; scores region now dead -> V ring

    // ---- phase 5: ctx = P @ V; 4-buffer V ring in scores region, wait<2> ----
    STAGE_V(0, 0); cp_commit();
    STAGE_V(1, 1); cp_commit();
    STAGE_V(2, 2); cp_commit();

    float cacc[2][4] = {{0.f,0.f,0.f,0.f},{0.f,0.f,0.f,0.f}};
    const int d0w = wi * 8;
#pragma unroll 1
    for (int kt = 0; kt < NTV; kt++) {
        cp_wait<2>();
        __syncthreads();                          // all consumed buf (kt+3)&3's old tile
        if (kt + 3 < NTV) { STAGE_V((kt + 3) & 3, kt + 3); }
        cp_commit();                              // uniform pending count

        const uint16_t* vb_ = (const uint16_t*)(smc + (kt & 3) * VSTG2);
        const int kb0 = kt * 128 + wg * 64;
#pragma unroll
        for (int sub = 0; sub < 4; sub++) {
            int k0 = kb0 + sub * 16;
            uint32_t a[4];
            const uint16_t* p0 = &pb[g * PBS + k0 + 2 * t];
            const uint16_t* p1 = &pb[(g + 8) * PBS + k0 + 2 * t];
            a[0] = *(const uint32_t*)p0;
            a[1] = *(const uint32_t*)p1;
            a[2] = *(const uint32_t*)(p0 + 8);
            a[3] = *(const uint32_t*)(p1 + 8);
            int kl = wg * 64 + sub * 16;
            const uint16_t* vr = &vb_[(d0w + g) * 136 + kl + 2 * t];
            uint32_t b0 = *(const uint32_t*)vr;
            uint32_t b1 = *(const uint32_t*)(vr + 8);
            mma16(cacc[sub & 1], a, b0, b1);
        }
    }

    // cross-group reduction in ring buf 0 region (tile 12 long consumed)
    float2 r0 = make_float2(cacc[0][0] + cacc[1][0], cacc[0][1] + cacc[1][1]);
    float2 r1 = make_float2(cacc[0][2] + cacc[1][2], cacc[0][3] + cacc[1][3]);
    float* red = (float*)smc;
    __syncthreads();
    if (wg == 1) {
        *(float2*)&red[g * 68 + d0w + 2 * t]       = r0;
        *(float2*)&red[(g + 8) * 68 + d0w + 2 * t] = r1;
    }
    __syncthreads();
    if (wg == 0) {
        float2 p0 = *(float2*)&red[g * 68 + d0w + 2 * t];
        float2 p1 = *(float2*)&red[(g + 8) * 68 + d0w + 2 * t];
        int qg   = qt * 16;
        int dcol = h * 64 + d0w + 2 * t;
        float c00 = r0.x + p0.x, c01 = r0.y + p0.y;
        float c10 = r1.x + p1.x, c11 = r1.y + p1.y;
        size_t o0 = ((size_t)b * Sq + qg + g) * Dq + dcol;
        size_t o1 = ((size_t)b * Sq + qg + g + 8) * Dq + dcol;
        uint16_t h00 = bfbits(c00), h01 = bfbits(c01);
        uint16_t h10 = bfbits(c10), h11 = bfbits(c11);
        *(uint32_t*)&ctxh[o0] = (uint32_t)h00 | ((uint32_t)h01 << 16);
        *(uint32_t*)&ctxh[o1] = (uint32_t)h10 | ((uint32_t)h11 << 16);
        uint16_t l00 = bfbits(c00 - bf2f(h00)), l01 = bfbits(c01 - bf2f(h01));
        uint16_t l10 = bfbits(c10 - bf2f(h10)), l11 = bfbits(c11 - bf2f(h11));
        *(uint32_t*)&ctxl[o0] = (uint32_t)l00 | ((uint32_t)l01 << 16);
        *(uint32_t*)&ctxl[o1] = (uint32_t)l10 | ((uint32_t)l11 << 16);
    }
#undef STAGE_K
#undef STAGE_V
}

// ---------------------------------------------------------------------------
__global__ __launch_bounds__(128)
void ln_kernel(const float* __restrict__ x, const float* __restrict__ gamma,
               const float* __restrict__ beta, float* __restrict__ out)
{
    const int row = blockIdx.x;
    const int tid = threadIdx.x;
    const float* xr = x + (size_t)row * 512;

    float4 v = *(const float4*)(xr + tid * 4);
    float s  = v.x + v.y + v.z + v.w;
    float ss = v.x * v.x + v.y * v.y + v.z * v.z + v.w * v.w;

    const int lane = tid & 31, warp = tid >> 5;
#pragma unroll
    for (int o = 16; o; o >>= 1) {
        s  += __shfl_xor_sync(0xffffffffu, s, o);
        ss += __shfl_xor_sync(0xffffffffu, ss, o);
    }
    __shared__ float sh_s[4], sh_ss[4];
    if (lane == 0) { sh_s[warp] = s; sh_ss[warp] = ss; }
    __syncthreads();
    float tot  = sh_s[0] + sh_s[1] + sh_s[2] + sh_s[3];
    float tots = sh_ss[0] + sh_ss[1] + sh_ss[2] + sh_ss[3];

    float mu   = tot * (1.0f / 512.0f);
    float var  = tots * (1.0f / 512.0f) - mu * mu;
    float rstd = rsqrtf(var + LN_EPS);

    float4 g  = *(const float4*)(gamma + tid * 4);
    float4 be = *(const float4*)(beta + tid * 4);
    float4 r;
    r.x = (v.x - mu) * rstd * g.x + be.x;
    r.y = (v.y - mu) * rstd * g.y + be.y;
    r.z = (v.z - mu) * rstd * g.z + be.z;
    r.w = (v.w - mu) * rstd * g.w + be.w;
    *(float4*)&out[(size_t)row * 512 + tid * 4] = r;
}

// ---------------------------------------------------------------------------
extern "C" void kernel_launch(void* const* d_in, const int* in_sizes, int n_in,
                              void* d_out, int out_size)
{
    const float*    inQ   = (const float*)d_in[0];
    const float*    inK   = (const float*)d_in[1];
    const float*    inV   = (const float*)d_in[2];
    const unsigned* mask  = (const unsigned*)d_in[3];
    const float*    WQ    = (const float*)d_in[4];
    const float*    WK    = (const float*)d_in[5];
    const float*    WV    = (const float*)d_in[6];
    const float*    Wfc   = (const float*)d_in[7];
    const float*    gamma = (const float*)d_in[8];
    const float*    beta  = (const float*)d_in[9];
    float* out = (float*)d_out;

    uint16_t *gQ, *gK, *gV;
    uint16_t *sQh, *sQl, *sKh, *sKl, *sVh, *sVl, *sCh, *sCl;
    uint16_t *wQh, *wQl, *wKh, *wKl, *wVh, *wVl, *wFh, *wFl;
    float *gpre;
    cudaGetSymbolAddress((void**)&gQ,   g_Q);
    cudaGetSymbolAddress((void**)&gK,   g_K);
    cudaGetSymbolAddress((void**)&gV,   g_V);
    cudaGetSymbolAddress((void**)&gpre, g_pre);
    cudaGetSymbolAddress((void**)&sQh, s_Qh);  cudaGetSymbolAddress((void**)&sQl, s_Ql);
    cudaGetSymbolAddress((void**)&sKh, s_Kh);  cudaGetSymbolAddress((void**)&sKl, s_Kl);
    cudaGetSymbolAddress((void**)&sVh, s_Vh);  cudaGetSymbolAddress((void**)&sVl, s_Vl);
    cudaGetSymbolAddress((void**)&sCh, s_Ch);  cudaGetSymbolAddress((void**)&sCl, s_Cl);
    cudaGetSymbolAddress((void**)&wQh, w_Qh);  cudaGetSymbolAddress((void**)&wQl, w_Ql);
    cudaGetSymbolAddress((void**)&wKh, w_Kh);  cudaGetSymbolAddress((void**)&wKl, w_Kl);
    cudaGetSymbolAddress((void**)&wVh, w_Vh);  cudaGetSymbolAddress((void**)&wVl, w_Vl);
    cudaGetSymbolAddress((void**)&wFh, w_Fh);  cudaGetSymbolAddress((void**)&wFl, w_Fl);

    const int n4 = (Bq * Sq * Dq) / 4;
    split_in3<<<dim3((n4 + 511) / 512, 3), 512>>>(
        (const float4*)inQ, (const float4*)inK, (const float4*)inV,
        (uint2*)sQh, (uint2*)sQl, (uint2*)sKh, (uint2*)sKl,
        (uint2*)sVh, (uint2*)sVl, n4);
    splitW4<<<dim3(16, 16, 4), dim3(32, 8)>>>(WQ, WK, WV, Wfc,
        wQh, wQl, wKh, wKl, wVh, wVl, wFh, wFl);

    const int SMG = (2 * 128 * 40 + 2 * 64 * 40) * 2 * 2;   // 61,440 B
    cudaFuncSetAttribute(gemm_qkv, cudaFuncAttributeMaxDynamicSharedMemorySize, SMG);
    cudaFuncSetAttribute(gemm_fc,  cudaFuncAttributeMaxDynamicSharedMemorySize, SMG);

    gemm_qkv<<<dim3(8, 64, 3), 256, SMG>>>(
        sQh, sQl, wQh, wQl, gQ,
        sKh, sKl, wKh, wKl, gK,
        sVh, sVl, wVh, wVl, gV);

    const size_t BSD  = (size_t)Bq * Sq * Dq;
    const size_t BHSS = (size_t)Bq * Hq * Sq * Sq;
    float* attn_ptr = ((size_t)out_size >= BSD + BHSS) ? (out + BSD) : nullptr;

    cudaFuncSetAttribute(attn_kernel, cudaFuncAttributeMaxDynamicSharedMemorySize, SMEM_ATTN);
    attn_kernel<<<dim3(32, 128), 512, SMEM_ATTN>>>(gQ, gK, gV, mask, attn_ptr, sCh, sCl);

    gemm_fc<<<dim3(8, 64), 256, SMG>>>(sCh, sCl, wFh, wFl, gpre, inQ);
    ln_kernel<<<Bq * Sq, 128>>>(gpre, gamma, beta, out);
}

// round 15
// speedup vs baseline: 1.1253x; 1.1253x over previous
#include <cuda_runtime.h>
#include <cuda_bf16.h>
#include <cstdint>

// Problem constants
#define Bq   4
#define Sq   2048
#define Dq   512
#define Hq   8
#define LN_EPS 1e-5f

// attn smem layout (bytes)
#define SST        2052
#define OFF_K      (16 * SST * 4)             // 131,328 : per-warp K double-buffers / pb
#define KWB        2176                       // per-warp K buf: 8 rows x 272B
#define VWB        2304                       // per-warp V buf: 8 rows x 144B (64 keys)
#define OFF_RED    73728                      // red region (after 16*2*VWB vbufs)
#define SMEM_ATTN  (OFF_K + 16 * 2 * KWB)     // 200,960
#define PBS        2056
#define NTK        16
#define NTV        16

// Scratch (device globals)
__device__ __align__(16) uint16_t g_Q[(size_t)Bq*Hq*Sq*128];   // bf16 [B,H,S,(hi64|lo64)]
__device__ __align__(16) uint16_t g_K[(size_t)Bq*Hq*Sq*128];
__device__ __align__(16) uint16_t g_V[(size_t)Bq*Hq*64*Sq];    // bf16 transposed [B,H,d,S]
__device__ float    g_pre[(size_t)Bq*Sq*Dq];
// bf16 hi/lo splits
__device__ __align__(16) uint16_t s_Qh[(size_t)Bq*Sq*Dq], s_Ql[(size_t)Bq*Sq*Dq];
__device__ __align__(16) uint16_t s_Kh[(size_t)Bq*Sq*Dq], s_Kl[(size_t)Bq*Sq*Dq];
__device__ __align__(16) uint16_t s_Vh[(size_t)Bq*Sq*Dq], s_Vl[(size_t)Bq*Sq*Dq];
__device__ __align__(16) uint16_t s_Ch[(size_t)Bq*Sq*Dq], s_Cl[(size_t)Bq*Sq*Dq];
__device__ __align__(16) uint16_t w_Qh[512*512], w_Ql[512*512];
__device__ __align__(16) uint16_t w_Kh[512*512], w_Kl[512*512];
__device__ __align__(16) uint16_t w_Vh[512*512], w_Vl[512*512];
__device__ __align__(16) uint16_t w_Fh[512*512], w_Fl[512*512];

// ---------------------------------------------------------------------------
__device__ __forceinline__ uint16_t bfbits(float x) {
    __nv_bfloat16 b = __float2bfloat16_rn(x);
    return *(uint16_t*)&b;
}
__device__ __forceinline__ float bf2f(uint16_t u) {
    __nv_bfloat16 b = *(__nv_bfloat16*)&u;
    return __bfloat162float(b);
}

__device__ __forceinline__ void mma16(float* c, const uint32_t* a, uint32_t b0, uint32_t b1) {
    asm volatile(
        "mma.sync.aligned.m16n8k16.row.col.f32.bf16.bf16.f32 "
        "{%0,%1,%2,%3}, {%4,%5,%6,%7}, {%8,%9}, {%0,%1,%2,%3};"
        : "+f"(c[0]), "+f"(c[1]), "+f"(c[2]), "+f"(c[3])
        : "r"(a[0]), "r"(a[1]), "r"(a[2]), "r"(a[3]), "r"(b0), "r"(b1));
}

__device__ __forceinline__ void cp16g(void* dst, const void* src) {
    uint32_t d = (uint32_t)__cvta_generic_to_shared(dst);
    asm volatile("cp.async.cg.shared.global [%0], [%1], 16;" :: "r"(d), "l"(src));
}
__device__ __forceinline__ void cp_commit() { asm volatile("cp.async.commit_group;"); }
template<int N> __device__ __forceinline__ void cp_wait() {
    asm volatile("cp.async.wait_group %0;" :: "n"(N));
}

// ---------------------------------------------------------------------------
// Split kernels (proven)
// ---------------------------------------------------------------------------
__global__ __launch_bounds__(512)
void split_in3(const float4* __restrict__ xQ, const float4* __restrict__ xK,
               const float4* __restrict__ xV,
               uint2* __restrict__ hQ, uint2* __restrict__ lQ,
               uint2* __restrict__ hK, uint2* __restrict__ lK,
               uint2* __restrict__ hV, uint2* __restrict__ lV, int n4)
{
    int i = blockIdx.x * 512 + threadIdx.x;
    if (i >= n4) return;
    const int y = blockIdx.y;
    const float4* x = (y == 0) ? xQ : (y == 1) ? xK : xV;
    uint2* hi = (y == 0) ? hQ : (y == 1) ? hK : hV;
    uint2* lo = (y == 0) ? lQ : (y == 1) ? lK : lV;
    float4 v = x[i];
    float vv[4] = {v.x, v.y, v.z, v.w};
    uint16_t h[4], l[4];
#pragma unroll
    for (int k = 0; k < 4; k++) {
        h[k] = bfbits(vv[k]);
        l[k] = bfbits(vv[k] - bf2f(h[k]));
    }
    hi[i] = *(uint2*)h;
    lo[i] = *(uint2*)l;
}

__global__ __launch_bounds__(256)
void splitW4(const float* __restrict__ W0, const float* __restrict__ W1,
             const float* __restrict__ W2, const float* __restrict__ W3,
             uint16_t* __restrict__ h0, uint16_t* __restrict__ l0,
             uint16_t* __restrict__ h1, uint16_t* __restrict__ l1,
             uint16_t* __restrict__ h2, uint16_t* __restrict__ l2,
             uint16_t* __restrict__ h3, uint16_t* __restrict__ l3)
{
    __shared__ float tile[32][33];
    const int z = blockIdx.z;
    const float* W = (z == 0) ? W0 : (z == 1) ? W1 : (z == 2) ? W2 : W3;
    uint16_t* th = (z == 0) ? h0 : (z == 1) ? h1 : (z == 2) ? h2 : h3;
    uint16_t* tl = (z == 0) ? l0 : (z == 1) ? l1 : (z == 2) ? l2 : l3;
    const int bx = blockIdx.x;
    const int by = blockIdx.y;
    const int x = threadIdx.x, y = threadIdx.y;
#pragma unroll
    for (int i = 0; i < 32; i += 8)
        tile[y + i][x] = W[(size_t)(by * 32 + y + i) * 512 + bx * 32 + x];
    __syncthreads();
#pragma unroll
    for (int i = 0; i < 32; i += 8) {
        float v = tile[x][y + i];
        uint16_t hb = bfbits(v);
        size_t o = (size_t)(bx * 32 + y + i) * 512 + by * 32 + x;
        th[o] = hb;
        tl[o] = bfbits(v - bf2f(hb));
    }
}

// ---------------------------------------------------------------------------
// PROVEN 4-term bf16 mainloop as a device function.
// ---------------------------------------------------------------------------
__device__ __forceinline__ void gemm4t_mainloop(
    uint16_t* sb,
    const uint16_t* __restrict__ Ah, const uint16_t* __restrict__ Al,
    const uint16_t* __restrict__ Bh, const uint16_t* __restrict__ Bl,
    int m0, int n0, int tid, int wm, int wn, int g, int t,
    float acc[2][4][4])
{
    const int AU = 128 * 40, BU = 64 * 40;
    const int BUF = 2 * AU + 2 * BU;

#define QK_STAGE(buf, kk_)                                                      \
    {                                                                           \
        uint16_t* _Ash = sb + (buf) * BUF;                                      \
        uint16_t* _Asl = _Ash + AU;                                             \
        uint16_t* _Bsh = _Ash + 2 * AU;                                         \
        uint16_t* _Bsl = _Bsh + BU;                                             \
        const int _k0 = (kk_) * 32;                                             \
        _Pragma("unroll")                                                       \
        for (int _j = 0; _j < 2; _j++) {                                        \
            int _c = tid + _j * 256, _r = _c >> 2, _q = _c & 3;                 \
            cp16g(_Ash + _r * 40 + _q * 8, Ah + (size_t)(m0 + _r) * 512 + _k0 + _q * 8); \
            cp16g(_Asl + _r * 40 + _q * 8, Al + (size_t)(m0 + _r) * 512 + _k0 + _q * 8); \
        }                                                                       \
        {                                                                       \
            int _r = tid >> 2, _q = tid & 3;                                    \
            cp16g(_Bsh + _r * 40 + _q * 8, Bh + (size_t)(n0 + _r) * 512 + _k0 + _q * 8); \
            cp16g(_Bsl + _r * 40 + _q * 8, Bl + (size_t)(n0 + _r) * 512 + _k0 + _q * 8); \
        }                                                                       \
    }

    QK_STAGE(0, 0);
    cp_commit();

#pragma unroll 1
    for (int kk = 0; kk < 16; kk++) {
        cp_wait<0>();
        __syncthreads();
        if (kk < 15) { QK_STAGE((kk + 1) & 1, kk + 1); }
        cp_commit();

        const uint16_t* Ash = sb + (kk & 1) * BUF;
        const uint16_t* Asl = Ash + AU;
        const uint16_t* Bsh = Ash + 2 * AU;
        const uint16_t* Bsl = Bsh + BU;

#pragma unroll
        for (int kc = 0; kc < 2; kc++) {
            uint32_t ah_[2][4], al_[2][4];
#pragma unroll
            for (int mi = 0; mi < 2; mi++) {
                int base = (wm * 32 + mi * 16 + g) * 40 + kc * 16 + 2 * t;
                ah_[mi][0] = *(const uint32_t*)&Ash[base];
                ah_[mi][1] = *(const uint32_t*)&Ash[base + 320];
                ah_[mi][2] = *(const uint32_t*)&Ash[base + 8];
                ah_[mi][3] = *(const uint32_t*)&Ash[base + 328];
                al_[mi][0] = *(const uint32_t*)&Asl[base];
                al_[mi][1] = *(const uint32_t*)&Asl[base + 320];
                al_[mi][2] = *(const uint32_t*)&Asl[base + 8];
                al_[mi][3] = *(const uint32_t*)&Asl[base + 328];
            }
#pragma unroll
            for (int nj = 0; nj < 4; nj++) {
                int nb = (wn * 32 + nj * 8 + g) * 40 + kc * 16 + 2 * t;
                uint32_t bh0 = *(const uint32_t*)&Bsh[nb];
                uint32_t bh1 = *(const uint32_t*)&Bsh[nb + 8];
                uint32_t bl0 = *(const uint32_t*)&Bsl[nb];
                uint32_t bl1 = *(const uint32_t*)&Bsl[nb + 8];
#pragma unroll
                for (int mi = 0; mi < 2; mi++) {
                    mma16(acc[mi][nj], ah_[mi], bh0, bh1);
                    mma16(acc[mi][nj], al_[mi], bh0, bh1);
                    mma16(acc[mi][nj], ah_[mi], bl0, bl1);
                    mma16(acc[mi][nj], al_[mi], bl0, bl1);
                }
            }
        }
    }
#undef QK_STAGE
}

// ---------------------------------------------------------------------------
// Merged Q/K/V projection GEMM (proven).
// ---------------------------------------------------------------------------
__global__ __launch_bounds__(256)
void gemm_qkv(const uint16_t* __restrict__ Qh, const uint16_t* __restrict__ Ql_,
              const uint16_t* __restrict__ WQh, const uint16_t* __restrict__ WQl,
              uint16_t* __restrict__ outQ,
              const uint16_t* __restrict__ Kh, const uint16_t* __restrict__ Kl_,
              const uint16_t* __restrict__ WKh, const uint16_t* __restrict__ WKl,
              uint16_t* __restrict__ outK,
              const uint16_t* __restrict__ Vh, const uint16_t* __restrict__ Vl_,
              const uint16_t* __restrict__ WVh, const uint16_t* __restrict__ WVl,
              uint16_t* __restrict__ outV)
{
    extern __shared__ uint16_t sb[];
    const int z = blockIdx.z;
    const uint16_t* Ah = (z == 0) ? Qh : (z == 1) ? Kh : Vh;
    const uint16_t* Al = (z == 0) ? Ql_ : (z == 1) ? Kl_ : Vl_;
    const uint16_t* Bh = (z == 0) ? WQh : (z == 1) ? WKh : WVh;
    const uint16_t* Bl = (z == 0) ? WQl : (z == 1) ? WKl : WVl;
    uint16_t* out      = (z == 0) ? outQ : (z == 1) ? outK : outV;
    const float scale  = (z == 0) ? 0.125f : 1.0f;

    const int tid = threadIdx.x;
    const int warp = tid >> 5, lane = tid & 31;
    const int g = lane >> 2, t = lane & 3;
    const int wm = warp >> 1, wn = warp & 1;
    const int h  = blockIdx.x;
    const int n0 = h * 64;
    const int m0 = blockIdx.y * 128;

    float acc[2][4][4];
#pragma unroll
    for (int i = 0; i < 2; i++)
#pragma unroll
        for (int j = 0; j < 4; j++)
#pragma unroll
            for (int r = 0; r < 4; r++) acc[i][j][r] = 0.f;

    gemm4t_mainloop(sb, Ah, Al, Bh, Bl, m0, n0, tid, wm, wn, g, t, acc);

    if (z < 2) {
#pragma unroll
        for (int mi = 0; mi < 2; mi++)
#pragma unroll
            for (int nj = 0; nj < 4; nj++) {
                int e = wn * 32 + nj * 8 + 2 * t;
#pragma unroll
                for (int half = 0; half < 2; half++) {
                    int m = m0 + wm * 32 + mi * 16 + g + half * 8;
                    int b = m >> 11, s = m & 2047;
                    size_t base = (((size_t)b * Hq + h) * Sq + s) * 128 + e;
                    float v0 = acc[mi][nj][half * 2]     * scale;
                    float v1 = acc[mi][nj][half * 2 + 1] * scale;
                    uint16_t h0 = bfbits(v0), h1 = bfbits(v1);
                    uint16_t l0 = bfbits(v0 - bf2f(h0)), l1 = bfbits(v1 - bf2f(h1));
                    *(uint32_t*)(out + base)      = (uint32_t)h0 | ((uint32_t)h1 << 16);
                    *(uint32_t*)(out + base + 64) = (uint32_t)l0 | ((uint32_t)l1 << 16);
                }
            }
    } else {
        const int b  = m0 >> 11;
        const size_t hb64 = (size_t)(b * Hq + h) * 64;
#pragma unroll
        for (int mi = 0; mi < 2; mi++)
#pragma unroll
            for (int nj = 0; nj < 4; nj++) {
#pragma unroll
                for (int r = 0; r < 4; r++) {
                    int m = m0 + wm * 32 + mi * 16 + g + (r >> 1) * 8;
                    int d = wn * 32 + nj * 8 + 2 * t + (r & 1);
                    int s = m & 2047;
                    out[(hb64 + d) * Sq + s] = bfbits(acc[mi][nj][r]);
                }
            }
    }
}

// fc GEMM (proven)
__global__ __launch_bounds__(256)
void gemm_fc(const uint16_t* __restrict__ Ah, const uint16_t* __restrict__ Al,
             const uint16_t* __restrict__ Bh, const uint16_t* __restrict__ Bl,
             float* __restrict__ out, const float* __restrict__ resid)
{
    extern __shared__ uint16_t sb[];
    const int tid = threadIdx.x;
    const int warp = tid >> 5, lane = tid & 31;
    const int g = lane >> 2, t = lane & 3;
    const int wm = warp >> 1, wn = warp & 1;
    const int n0 = blockIdx.x * 64;
    const int m0 = blockIdx.y * 128;

    float acc[2][4][4];
#pragma unroll
    for (int i = 0; i < 2; i++)
#pragma unroll
        for (int j = 0; j < 4; j++)
#pragma unroll
            for (int r = 0; r < 4; r++) acc[i][j][r] = 0.f;

    gemm4t_mainloop(sb, Ah, Al, Bh, Bl, m0, n0, tid, wm, wn, g, t, acc);

#pragma unroll
    for (int mi = 0; mi < 2; mi++)
#pragma unroll
        for (int nj = 0; nj < 4; nj++) {
            int n = n0 + wn * 32 + nj * 8 + 2 * t;
#pragma unroll
            for (int half = 0; half < 2; half++) {
                int m = m0 + wm * 32 + mi * 16 + g + half * 8;
                float2 rv = *(const float2*)&resid[(size_t)m * 512 + n];
                *(float2*)&out[(size_t)m * 512 + n] =
                    make_float2(acc[mi][nj][half * 2] + rv.x,
                                acc[mi][nj][half * 2 + 1] + rv.y);
            }
        }
}

// ---------------------------------------------------------------------------
// Fused attention — barrier-free per-warp pipelines.
// Each warp double-buffers ITS OWN K slice (8 keys) / V slice (8 d-rows x 64
// keys) and syncs via its own cp.async groups; no __syncthreads in the loops.
// Smem overlays: [0, 131328): scores / (qs prologue) / (vbufs + red, phase 5)
//                [131328, 200960): per-warp K bufs (phase 2) / pb (later)
// ---------------------------------------------------------------------------
__global__ __launch_bounds__(512, 1)
void attn_kernel(const uint16_t* __restrict__ Qm, const uint16_t* __restrict__ Km,
                 const uint16_t* __restrict__ Vt, const unsigned* __restrict__ mask,
                 float* __restrict__ attn_out,
                 uint16_t* __restrict__ ctxh, uint16_t* __restrict__ ctxl)
{
    extern __shared__ char smc[];
    float*    scores = (float*)smc;
    uint16_t* pb     = (uint16_t*)(smc + OFF_K);
    uint16_t* qs     = (uint16_t*)smc;           // prologue only

    const int bh  = blockIdx.x;
    const int qt  = blockIdx.y;
    const int b   = bh >> 3;
    const int h   = bh & 7;
    const int tid = threadIdx.x;
    const int warp = tid >> 5;
    const int lane = tid & 31;
    const int g = lane >> 2;
    const int t = lane & 3;
    const int wg = warp >> 3;
    const int wi = warp & 7;
    const int n0 = warp * 8;
    const int d0w = wi * 8;

    const uint16_t* KB = Km + (size_t)bh * Sq * 128;
    const uint16_t* VB = Vt + (size_t)bh * 64 * Sq;

    char* kw = smc + OFF_K + warp * (2 * KWB);   // this warp's K buffers
    char* vw = smc + warp * (2 * VWB);           // this warp's V buffers (scores region)

    // per-warp K stage: 8 keys x 256B = 128 chunks, 4 per lane
#define STAGE_KW(buf, kt_)                                                   \
    {                                                                        \
        char* _d = kw + (buf) * KWB;                                         \
        const uint16_t* _s = KB + (size_t)((kt_) * 128 + n0) * 128;          \
        _Pragma("unroll")                                                    \
        for (int _j = 0; _j < 4; _j++) {                                     \
            int _c = lane + _j * 32;                                         \
            int _r = _c >> 4, _c16 = _c & 15;                                \
            cp16g(_d + _r * 272 + _c16 * 16, _s + _r * 128 + _c16 * 8);      \
        }                                                                    \
    }
    // per-warp V stage: 8 d-rows x 64 keys (128B/row) = 64 chunks, 2 per lane
#define STAGE_VW(buf, kt_)                                                   \
    {                                                                        \
        char* _d = vw + (buf) * VWB;                                         \
        const uint16_t* _s = VB + (size_t)d0w * Sq + (kt_) * 128 + wg * 64;  \
        _Pragma("unroll")                                                    \
        for (int _j = 0; _j < 2; _j++) {                                     \
            int _c = lane + _j * 32;                                         \
            int _r = _c >> 3, _c16 = _c & 7;                                 \
            cp16g(_d + _r * 144 + _c16 * 16, _s + (size_t)_r * Sq + _c16 * 8);\
        }                                                                    \
    }

    // prologue: per-warp K tile 0; Q (cooperative) into qs
    STAGE_KW(0, 0);
    cp_commit();
    if (tid < 256) {
        int r = tid >> 4, c16 = tid & 15;
        cp16g((char*)qs + r * 272 + c16 * 16,
              Qm + (size_t)bh * Sq * 128 + (size_t)(qt * 16 + r) * 128 + c16 * 8);
    }
    cp_commit();
    cp_wait<0>();
    __syncthreads();

    uint32_t qh[4][4], ql[4][4];
#pragma unroll
    for (int ch = 0; ch < 4; ch++) {
        int c0 = ch * 16 + 2 * t;
        qh[ch][0] = *(uint32_t*)&qs[g * 136 + c0];
        qh[ch][1] = *(uint32_t*)&qs[(g + 8) * 136 + c0];
        qh[ch][2] = *(uint32_t*)&qs[g * 136 + c0 + 8];
        qh[ch][3] = *(uint32_t*)&qs[(g + 8) * 136 + c0 + 8];
        ql[ch][0] = *(uint32_t*)&qs[g * 136 + c0 + 64];
        ql[ch][1] = *(uint32_t*)&qs[(g + 8) * 136 + c0 + 64];
        ql[ch][2] = *(uint32_t*)&qs[g * 136 + c0 + 72];
        ql[ch][3] = *(uint32_t*)&qs[(g + 8) * 136 + c0 + 72];
    }
    __syncthreads();   // qs fully consumed before any scores writes

    // ---- phase 2: scores = Q @ K^T — PER-WARP pipeline, no CTA barriers ----
#pragma unroll 1
    for (int kt = 0; kt < NTK; kt++) {
        if (kt + 1 < NTK) { STAGE_KW((kt + 1) & 1, kt + 1); }
        cp_commit();
        cp_wait<1>();                             // this warp's tile kt landed

        const uint16_t* kb_ = (const uint16_t*)(kw + (kt & 1) * KWB);
        float acc[2][4] = {{0.f,0.f,0.f,0.f},{0.f,0.f,0.f,0.f}};
#pragma unroll
        for (int ch = 0; ch < 4; ch++) {
            const uint16_t* kr = &kb_[g * 136 + ch * 16 + 2 * t];
            uint32_t bh0 = *(const uint32_t*)kr;
            uint32_t bh1 = *(const uint32_t*)(kr + 8);
            uint32_t bl0 = *(const uint32_t*)(kr + 64);
            uint32_t bl1 = *(const uint32_t*)(kr + 72);
            mma16(acc[ch & 1], qh[ch], bh0, bh1);
            mma16(acc[ch & 1], ql[ch], bh0, bh1);
            mma16(acc[ch & 1], qh[ch], bl0, bl1);
        }
        int col = kt * 128 + n0 + 2 * t;
        *(float2*)&scores[g * SST + col]       = make_float2(acc[0][0] + acc[1][0], acc[0][1] + acc[1][1]);
        *(float2*)&scores[(g + 8) * SST + col] = make_float2(acc[0][2] + acc[1][2], acc[0][3] + acc[1][3]);
    }
    __syncthreads();   // all scores visible; kbuf region free for pb

    // ---- phase 3/4: mask+exp+sum, normalize + attn write + bf16 P pack ----
    {
        const int row = warp;
        const int qg  = qt * 16 + row;
        const uint2* mrow2 = (const uint2*)(mask + ((size_t)b * Sq + qg) * Sq);
        float2* srow2 = (float2*)(scores + row * SST);

        float sum = 0.f;
#pragma unroll 4
        for (int i = lane; i < 1024; i += 32) {
            float2 s = srow2[i];
            uint2  m = mrow2[i];
            float px = m.x ? 0.f : __expf(s.x);
            float py = m.y ? 0.f : __expf(s.y);
            srow2[i] = make_float2(px, py);
            sum += px + py;
        }
#pragma unroll
        for (int o = 16; o; o >>= 1) sum += __shfl_xor_sync(0xffffffffu, sum, o);
        float inv = 1.0f / sum;

        uint32_t* prow = (uint32_t*)&pb[row * PBS];
        if (attn_out) {
            float2* arow2 = (float2*)(attn_out + ((size_t)bh * Sq + qg) * Sq);
#pragma unroll 4
            for (int i = lane; i < 1024; i += 32) {
                float2 p = srow2[i];
                float2 pn = make_float2(p.x * inv, p.y * inv);
                arow2[i] = pn;
                __nv_bfloat162 h2 = __float22bfloat162_rn(pn);
                prow[i] = *(uint32_t*)&h2;
            }
        } else {
#pragma unroll 4
            for (int i = lane; i < 1024; i += 32) {
                float2 p = srow2[i];
                float2 pn = make_float2(p.x * inv, p.y * inv);
                __nv_bfloat162 h2 = __float22bfloat162_rn(pn);
                prow[i] = *(uint32_t*)&h2;
            }
        }
    }
    __syncthreads();   // pb complete; scores region dead -> per-warp V buffers

    // ---- phase 5: ctx = P @ V — PER-WARP pipeline, no CTA barriers ----
    STAGE_VW(0, 0);
    cp_commit();

    float cacc[2][4] = {{0.f,0.f,0.f,0.f},{0.f,0.f,0.f,0.f}};
#pragma unroll 1
    for (int kt = 0; kt < NTV; kt++) {
        if (kt + 1 < NTV) { STAGE_VW((kt + 1) & 1, kt + 1); }
        cp_commit();
        cp_wait<1>();                             // this warp's tile kt landed

        const uint16_t* vb_ = (const uint16_t*)(vw + (kt & 1) * VWB);
        const int kb0 = kt * 128 + wg * 64;
#pragma unroll
        for (int sub = 0; sub < 4; sub++) {
            int k0 = kb0 + sub * 16;
            uint32_t a[4];
            const uint16_t* p0 = &pb[g * PBS + k0 + 2 * t];
            const uint16_t* p1 = &pb[(g + 8) * PBS + k0 + 2 * t];
            a[0] = *(const uint32_t*)p0;
            a[1] = *(const uint32_t*)p1;
            a[2] = *(const uint32_t*)(p0 + 8);
            a[3] = *(const uint32_t*)(p1 + 8);
            const uint16_t* vr = &vb_[g * 72 + sub * 16 + 2 * t];
            uint32_t b0 = *(const uint32_t*)vr;
            uint32_t b1 = *(const uint32_t*)(vr + 8);
            mma16(cacc[sub & 1], a, b0, b1);
        }
    }

    // cross-group reduction in red region (after vbufs; exact fp32)
    float2 r0 = make_float2(cacc[0][0] + cacc[1][0], cacc[0][1] + cacc[1][1]);
    float2 r1 = make_float2(cacc[0][2] + cacc[1][2], cacc[0][3] + cacc[1][3]);
    float* red = (float*)(smc + OFF_RED);
    __syncthreads();
    if (wg == 1) {
        *(float2*)&red[g * 68 + d0w + 2 * t]       = r0;
        *(float2*)&red[(g + 8) * 68 + d0w + 2 * t] = r1;
    }
    __syncthreads();
    if (wg == 0) {
        float2 p0 = *(float2*)&red[g * 68 + d0w + 2 * t];
        float2 p1 = *(float2*)&red[(g + 8) * 68 + d0w + 2 * t];
        int qg   = qt * 16;
        int dcol = h * 64 + d0w + 2 * t;
        float c00 = r0.x + p0.x, c01 = r0.y + p0.y;
        float c10 = r1.x + p1.x, c11 = r1.y + p1.y;
        size_t o0 = ((size_t)b * Sq + qg + g) * Dq + dcol;
        size_t o1 = ((size_t)b * Sq + qg + g + 8) * Dq + dcol;
        uint16_t h00 = bfbits(c00), h01 = bfbits(c01);
        uint16_t h10 = bfbits(c10), h11 = bfbits(c11);
        *(uint32_t*)&ctxh[o0] = (uint32_t)h00 | ((uint32_t)h01 << 16);
        *(uint32_t*)&ctxh[o1] = (uint32_t)h10 | ((uint32_t)h11 << 16);
        uint16_t l00 = bfbits(c00 - bf2f(h00)), l01 = bfbits(c01 - bf2f(h01));
        uint16_t l10 = bfbits(c10 - bf2f(h10)), l11 = bfbits(c11 - bf2f(h11));
        *(uint32_t*)&ctxl[o0] = (uint32_t)l00 | ((uint32_t)l01 << 16);
        *(uint32_t*)&ctxl[o1] = (uint32_t)l10 | ((uint32_t)l11 << 16);
    }
#undef STAGE_KW
#undef STAGE_VW
}

// ---------------------------------------------------------------------------
__global__ __launch_bounds__(128)
void ln_kernel(const float* __restrict__ x, const float* __restrict__ gamma,
               const float* __restrict__ beta, float* __restrict__ out)
{
    const int row = blockIdx.x;
    const int tid = threadIdx.x;
    const float* xr = x + (size_t)row * 512;

    float4 v = *(const float4*)(xr + tid * 4);
    float s  = v.x + v.y + v.z + v.w;
    float ss = v.x * v.x + v.y * v.y + v.z * v.z + v.w * v.w;

    const int lane = tid & 31, warp = tid >> 5;
#pragma unroll
    for (int o = 16; o; o >>= 1) {
        s  += __shfl_xor_sync(0xffffffffu, s, o);
        ss += __shfl_xor_sync(0xffffffffu, ss, o);
    }
    __shared__ float sh_s[4], sh_ss[4];
    if (lane == 0) { sh_s[warp] = s; sh_ss[warp] = ss; }
    __syncthreads();
    float tot  = sh_s[0] + sh_s[1] + sh_s[2] + sh_s[3];
    float tots = sh_ss[0] + sh_ss[1] + sh_ss[2] + sh_ss[3];

    float mu   = tot * (1.0f / 512.0f);
    float var  = tots * (1.0f / 512.0f) - mu * mu;
    float rstd = rsqrtf(var + LN_EPS);

    float4 g  = *(const float4*)(gamma + tid * 4);
    float4 be = *(const float4*)(beta + tid * 4);
    float4 r;
    r.x = (v.x - mu) * rstd * g.x + be.x;
    r.y = (v.y - mu) * rstd * g.y + be.y;
    r.z = (v.z - mu) * rstd * g.z + be.z;
    r.w = (v.w - mu) * rstd * g.w + be.w;
    *(float4*)&out[(size_t)row * 512 + tid * 4] = r;
}

// ---------------------------------------------------------------------------
extern "C" void kernel_launch(void* const* d_in, const int* in_sizes, int n_in,
                              void* d_out, int out_size)
{
    const float*    inQ   = (const float*)d_in[0];
    const float*    inK   = (const float*)d_in[1];
    const float*    inV   = (const float*)d_in[2];
    const unsigned* mask  = (const unsigned*)d_in[3];
    const float*    WQ    = (const float*)d_in[4];
    const float*    WK    = (const float*)d_in[5];
    const float*    WV    = (const float*)d_in[6];
    const float*    Wfc   = (const float*)d_in[7];
    const float*    gamma = (const float*)d_in[8];
    const float*    beta  = (const float*)d_in[9];
    float* out = (float*)d_out;

    uint16_t *gQ, *gK, *gV;
    uint16_t *sQh, *sQl, *sKh, *sKl, *sVh, *sVl, *sCh, *sCl;
    uint16_t *wQh, *wQl, *wKh, *wKl, *wVh, *wVl, *wFh, *wFl;
    float *gpre;
    cudaGetSymbolAddress((void**)&gQ,   g_Q);
    cudaGetSymbolAddress((void**)&gK,   g_K);
    cudaGetSymbolAddress((void**)&gV,   g_V);
    cudaGetSymbolAddress((void**)&gpre, g_pre);
    cudaGetSymbolAddress((void**)&sQh, s_Qh);  cudaGetSymbolAddress((void**)&sQl, s_Ql);
    cudaGetSymbolAddress((void**)&sKh, s_Kh);  cudaGetSymbolAddress((void**)&sKl, s_Kl);
    cudaGetSymbolAddress((void**)&sVh, s_Vh);  cudaGetSymbolAddress((void**)&sVl, s_Vl);
    cudaGetSymbolAddress((void**)&sCh, s_Ch);  cudaGetSymbolAddress((void**)&sCl, s_Cl);
    cudaGetSymbolAddress((void**)&wQh, w_Qh);  cudaGetSymbolAddress((void**)&wQl, w_Ql);
    cudaGetSymbolAddress((void**)&wKh, w_Kh);  cudaGetSymbolAddress((void**)&wKl, w_Kl);
    cudaGetSymbolAddress((void**)&wVh, w_Vh);  cudaGetSymbolAddress((void**)&wVl, w_Vl);
    cudaGetSymbolAddress((void**)&wFh, w_Fh);  cudaGetSymbolAddress((void**)&wFl, w_Fl);

    const int n4 = (Bq * Sq * Dq) / 4;
    split_in3<<<dim3((n4 + 511) / 512, 3), 512>>>(
        (const float4*)inQ, (const float4*)inK, (const float4*)inV,
        (uint2*)sQh, (uint2*)sQl, (uint2*)sKh, (uint2*)sKl,
        (uint2*)sVh, (uint2*)sVl, n4);
    splitW4<<<dim3(16, 16, 4), dim3(32, 8)>>>(WQ, WK, WV, Wfc,
        wQh, wQl, wKh, wKl, wVh, wVl, wFh, wFl);

    const int SMG = (2 * 128 * 40 + 2 * 64 * 40) * 2 * 2;   // 61,440 B
    cudaFuncSetAttribute(gemm_qkv, cudaFuncAttributeMaxDynamicSharedMemorySize, SMG);
    cudaFuncSetAttribute(gemm_fc,  cudaFuncAttributeMaxDynamicSharedMemorySize, SMG);

    gemm_qkv<<<dim3(8, 64, 3), 256, SMG>>>(
        sQh, sQl, wQh, wQl, gQ,
        sKh, sKl, wKh, wKl, gK,
        sVh, sVl, wVh, wVl, gV);

    const size_t BSD  = (size_t)Bq * Sq * Dq;
    const size_t BHSS = (size_t)Bq * Hq * Sq * Sq;
    float* attn_ptr = ((size_t)out_size >= BSD + BHSS) ? (out + BSD) : nullptr;

    cudaFuncSetAttribute(attn_kernel, cudaFuncAttributeMaxDynamicSharedMemorySize, SMEM_ATTN);
    attn_kernel<<<dim3(32, 128), 512, SMEM_ATTN>>>(gQ, gK, gV, mask, attn_ptr, sCh, sCl);

    gemm_fc<<<dim3(8, 64), 256, SMG>>>(sCh, sCl, wFh, wFl, gpre, inQ);
    ln_kernel<<<Bq * Sq, 128>>>(gpre, gamma, beta, out);
}

// round 16
// speedup vs baseline: 1.1508x; 1.0227x over previous
#include <cuda_runtime.h>
#include <cuda_bf16.h>
#include <cstdint>

// Problem constants
#define Bq   4
#define Sq   2048
#define Dq   512
#define Hq   8
#define LN_EPS 1e-5f

// attn smem layout (bytes)
#define SST        2052
#define OFF_K      (16 * SST * 4)             // 131,328 : per-warp K double-buffers / pb
#define KWB        2176                       // per-warp K buf: 8 rows x 272B
#define VWB        2304                       // per-warp V buf: 8 rows x 144B (64 keys)
#define OFF_RED    (3 * 16 * VWB)             // 110,592 : red after 3-deep vbufs
#define SMEM_ATTN  (OFF_K + 16 * 2 * KWB)     // 200,960
#define PBS        2056
#define NTK        16
#define NTV        16

// Scratch (device globals)
__device__ __align__(16) uint16_t g_Q[(size_t)Bq*Hq*Sq*128];   // bf16 [B,H,S,(hi64|lo64)]
__device__ __align__(16) uint16_t g_K[(size_t)Bq*Hq*Sq*128];
__device__ __align__(16) uint16_t g_V[(size_t)Bq*Hq*64*Sq];    // bf16 transposed [B,H,d,S]
__device__ float    g_pre[(size_t)Bq*Sq*Dq];
// bf16 hi/lo splits
__device__ __align__(16) uint16_t s_Qh[(size_t)Bq*Sq*Dq], s_Ql[(size_t)Bq*Sq*Dq];
__device__ __align__(16) uint16_t s_Kh[(size_t)Bq*Sq*Dq], s_Kl[(size_t)Bq*Sq*Dq];
__device__ __align__(16) uint16_t s_Vh[(size_t)Bq*Sq*Dq], s_Vl[(size_t)Bq*Sq*Dq];
__device__ __align__(16) uint16_t s_Ch[(size_t)Bq*Sq*Dq], s_Cl[(size_t)Bq*Sq*Dq];
__device__ __align__(16) uint16_t w_Qh[512*512], w_Ql[512*512];
__device__ __align__(16) uint16_t w_Kh[512*512], w_Kl[512*512];
__device__ __align__(16) uint16_t w_Vh[512*512], w_Vl[512*512];
__device__ __align__(16) uint16_t w_Fh[512*512], w_Fl[512*512];

// ---------------------------------------------------------------------------
__device__ __forceinline__ uint16_t bfbits(float x) {
    __nv_bfloat16 b = __float2bfloat16_rn(x);
    return *(uint16_t*)&b;
}
__device__ __forceinline__ float bf2f(uint16_t u) {
    __nv_bfloat16 b = *(__nv_bfloat16*)&u;
    return __bfloat162float(b);
}

__device__ __forceinline__ void mma16(float* c, const uint32_t* a, uint32_t b0, uint32_t b1) {
    asm volatile(
        "mma.sync.aligned.m16n8k16.row.col.f32.bf16.bf16.f32 "
        "{%0,%1,%2,%3}, {%4,%5,%6,%7}, {%8,%9}, {%0,%1,%2,%3};"
        : "+f"(c[0]), "+f"(c[1]), "+f"(c[2]), "+f"(c[3])
        : "r"(a[0]), "r"(a[1]), "r"(a[2]), "r"(a[3]), "r"(b0), "r"(b1));
}

__device__ __forceinline__ void cp16g(void* dst, const void* src) {
    uint32_t d = (uint32_t)__cvta_generic_to_shared(dst);
    asm volatile("cp.async.cg.shared.global [%0], [%1], 16;" :: "r"(d), "l"(src));
}
__device__ __forceinline__ void cp_commit() { asm volatile("cp.async.commit_group;"); }
template<int N> __device__ __forceinline__ void cp_wait() {
    asm volatile("cp.async.wait_group %0;" :: "n"(N));
}

// ---------------------------------------------------------------------------
// Split kernels (proven)
// ---------------------------------------------------------------------------
__global__ __launch_bounds__(512)
void split_in3(const float4* __restrict__ xQ, const float4* __restrict__ xK,
               const float4* __restrict__ xV,
               uint2* __restrict__ hQ, uint2* __restrict__ lQ,
               uint2* __restrict__ hK, uint2* __restrict__ lK,
               uint2* __restrict__ hV, uint2* __restrict__ lV, int n4)
{
    int i = blockIdx.x * 512 + threadIdx.x;
    if (i >= n4) return;
    const int y = blockIdx.y;
    const float4* x = (y == 0) ? xQ : (y == 1) ? xK : xV;
    uint2* hi = (y == 0) ? hQ : (y == 1) ? hK : hV;
    uint2* lo = (y == 0) ? lQ : (y == 1) ? lK : lV;
    float4 v = x[i];
    float vv[4] = {v.x, v.y, v.z, v.w};
    uint16_t h[4], l[4];
#pragma unroll
    for (int k = 0; k < 4; k++) {
        h[k] = bfbits(vv[k]);
        l[k] = bfbits(vv[k] - bf2f(h[k]));
    }
    hi[i] = *(uint2*)h;
    lo[i] = *(uint2*)l;
}

__global__ __launch_bounds__(256)
void splitW4(const float* __restrict__ W0, const float* __restrict__ W1,
             const float* __restrict__ W2, const float* __restrict__ W3,
             uint16_t* __restrict__ h0, uint16_t* __restrict__ l0,
             uint16_t* __restrict__ h1, uint16_t* __restrict__ l1,
             uint16_t* __restrict__ h2, uint16_t* __restrict__ l2,
             uint16_t* __restrict__ h3, uint16_t* __restrict__ l3)
{
    __shared__ float tile[32][33];
    const int z = blockIdx.z;
    const float* W = (z == 0) ? W0 : (z == 1) ? W1 : (z == 2) ? W2 : W3;
    uint16_t* th = (z == 0) ? h0 : (z == 1) ? h1 : (z == 2) ? h2 : h3;
    uint16_t* tl = (z == 0) ? l0 : (z == 1) ? l1 : (z == 2) ? l2 : l3;
    const int bx = blockIdx.x;
    const int by = blockIdx.y;
    const int x = threadIdx.x, y = threadIdx.y;
#pragma unroll
    for (int i = 0; i < 32; i += 8)
        tile[y + i][x] = W[(size_t)(by * 32 + y + i) * 512 + bx * 32 + x];
    __syncthreads();
#pragma unroll
    for (int i = 0; i < 32; i += 8) {
        float v = tile[x][y + i];
        uint16_t hb = bfbits(v);
        size_t o = (size_t)(bx * 32 + y + i) * 512 + by * 32 + x;
        th[o] = hb;
        tl[o] = bfbits(v - bf2f(hb));
    }
}

// ---------------------------------------------------------------------------
// PROVEN 4-term bf16 mainloop as a device function.
// ---------------------------------------------------------------------------
__device__ __forceinline__ void gemm4t_mainloop(
    uint16_t* sb,
    const uint16_t* __restrict__ Ah, const uint16_t* __restrict__ Al,
    const uint16_t* __restrict__ Bh, const uint16_t* __restrict__ Bl,
    int m0, int n0, int tid, int wm, int wn, int g, int t,
    float acc[2][4][4])
{
    const int AU = 128 * 40, BU = 64 * 40;
    const int BUF = 2 * AU + 2 * BU;

#define QK_STAGE(buf, kk_)                                                      \
    {                                                                           \
        uint16_t* _Ash = sb + (buf) * BUF;                                      \
        uint16_t* _Asl = _Ash + AU;                                             \
        uint16_t* _Bsh = _Ash + 2 * AU;                                         \
        uint16_t* _Bsl = _Bsh + BU;                                             \
        const int _k0 = (kk_) * 32;                                             \
        _Pragma("unroll")                                                       \
        for (int _j = 0; _j < 2; _j++) {                                        \
            int _c = tid + _j * 256, _r = _c >> 2, _q = _c & 3;                 \
            cp16g(_Ash + _r * 40 + _q * 8, Ah + (size_t)(m0 + _r) * 512 + _k0 + _q * 8); \
            cp16g(_Asl + _r * 40 + _q * 8, Al + (size_t)(m0 + _r) * 512 + _k0 + _q * 8); \
        }                                                                       \
        {                                                                       \
            int _r = tid >> 2, _q = tid & 3;                                    \
            cp16g(_Bsh + _r * 40 + _q * 8, Bh + (size_t)(n0 + _r) * 512 + _k0 + _q * 8); \
            cp16g(_Bsl + _r * 40 + _q * 8, Bl + (size_t)(n0 + _r) * 512 + _k0 + _q * 8); \
        }                                                                       \
    }

    QK_STAGE(0, 0);
    cp_commit();

#pragma unroll 1
    for (int kk = 0; kk < 16; kk++) {
        cp_wait<0>();
        __syncthreads();
        if (kk < 15) { QK_STAGE((kk + 1) & 1, kk + 1); }
        cp_commit();

        const uint16_t* Ash = sb + (kk & 1) * BUF;
        const uint16_t* Asl = Ash + AU;
        const uint16_t* Bsh = Ash + 2 * AU;
        const uint16_t* Bsl = Bsh + BU;

#pragma unroll
        for (int kc = 0; kc < 2; kc++) {
            uint32_t ah_[2][4], al_[2][4];
#pragma unroll
            for (int mi = 0; mi < 2; mi++) {
                int base = (wm * 32 + mi * 16 + g) * 40 + kc * 16 + 2 * t;
                ah_[mi][0] = *(const uint32_t*)&Ash[base];
                ah_[mi][1] = *(const uint32_t*)&Ash[base + 320];
                ah_[mi][2] = *(const uint32_t*)&Ash[base + 8];
                ah_[mi][3] = *(const uint32_t*)&Ash[base + 328];
                al_[mi][0] = *(const uint32_t*)&Asl[base];
                al_[mi][1] = *(const uint32_t*)&Asl[base + 320];
                al_[mi][2] = *(const uint32_t*)&Asl[base + 8];
                al_[mi][3] = *(const uint32_t*)&Asl[base + 328];
            }
#pragma unroll
            for (int nj = 0; nj < 4; nj++) {
                int nb = (wn * 32 + nj * 8 + g) * 40 + kc * 16 + 2 * t;
                uint32_t bh0 = *(const uint32_t*)&Bsh[nb];
                uint32_t bh1 = *(const uint32_t*)&Bsh[nb + 8];
                uint32_t bl0 = *(const uint32_t*)&Bsl[nb];
                uint32_t bl1 = *(const uint32_t*)&Bsl[nb + 8];
#pragma unroll
                for (int mi = 0; mi < 2; mi++) {
                    mma16(acc[mi][nj], ah_[mi], bh0, bh1);
                    mma16(acc[mi][nj], al_[mi], bh0, bh1);
                    mma16(acc[mi][nj], ah_[mi], bl0, bl1);
                    mma16(acc[mi][nj], al_[mi], bl0, bl1);
                }
            }
        }
    }
#undef QK_STAGE
}

// ---------------------------------------------------------------------------
// Merged Q/K/V projection GEMM (proven).
// ---------------------------------------------------------------------------
__global__ __launch_bounds__(256)
void gemm_qkv(const uint16_t* __restrict__ Qh, const uint16_t* __restrict__ Ql_,
              const uint16_t* __restrict__ WQh, const uint16_t* __restrict__ WQl,
              uint16_t* __restrict__ outQ,
              const uint16_t* __restrict__ Kh, const uint16_t* __restrict__ Kl_,
              const uint16_t* __restrict__ WKh, const uint16_t* __restrict__ WKl,
              uint16_t* __restrict__ outK,
              const uint16_t* __restrict__ Vh, const uint16_t* __restrict__ Vl_,
              const uint16_t* __restrict__ WVh, const uint16_t* __restrict__ WVl,
              uint16_t* __restrict__ outV)
{
    extern __shared__ uint16_t sb[];
    const int z = blockIdx.z;
    const uint16_t* Ah = (z == 0) ? Qh : (z == 1) ? Kh : Vh;
    const uint16_t* Al = (z == 0) ? Ql_ : (z == 1) ? Kl_ : Vl_;
    const uint16_t* Bh = (z == 0) ? WQh : (z == 1) ? WKh : WVh;
    const uint16_t* Bl = (z == 0) ? WQl : (z == 1) ? WKl : WVl;
    uint16_t* out      = (z == 0) ? outQ : (z == 1) ? outK : outV;
    const float scale  = (z == 0) ? 0.125f : 1.0f;

    const int tid = threadIdx.x;
    const int warp = tid >> 5, lane = tid & 31;
    const int g = lane >> 2, t = lane & 3;
    const int wm = warp >> 1, wn = warp & 1;
    const int h  = blockIdx.x;
    const int n0 = h * 64;
    const int m0 = blockIdx.y * 128;

    float acc[2][4][4];
#pragma unroll
    for (int i = 0; i < 2; i++)
#pragma unroll
        for (int j = 0; j < 4; j++)
#pragma unroll
            for (int r = 0; r < 4; r++) acc[i][j][r] = 0.f;

    gemm4t_mainloop(sb, Ah, Al, Bh, Bl, m0, n0, tid, wm, wn, g, t, acc);

    if (z < 2) {
#pragma unroll
        for (int mi = 0; mi < 2; mi++)
#pragma unroll
            for (int nj = 0; nj < 4; nj++) {
                int e = wn * 32 + nj * 8 + 2 * t;
#pragma unroll
                for (int half = 0; half < 2; half++) {
                    int m = m0 + wm * 32 + mi * 16 + g + half * 8;
                    int b = m >> 11, s = m & 2047;
                    size_t base = (((size_t)b * Hq + h) * Sq + s) * 128 + e;
                    float v0 = acc[mi][nj][half * 2]     * scale;
                    float v1 = acc[mi][nj][half * 2 + 1] * scale;
                    uint16_t h0 = bfbits(v0), h1 = bfbits(v1);
                    uint16_t l0 = bfbits(v0 - bf2f(h0)), l1 = bfbits(v1 - bf2f(h1));
                    *(uint32_t*)(out + base)      = (uint32_t)h0 | ((uint32_t)h1 << 16);
                    *(uint32_t*)(out + base + 64) = (uint32_t)l0 | ((uint32_t)l1 << 16);
                }
            }
    } else {
        const int b  = m0 >> 11;
        const size_t hb64 = (size_t)(b * Hq + h) * 64;
#pragma unroll
        for (int mi = 0; mi < 2; mi++)
#pragma unroll
            for (int nj = 0; nj < 4; nj++) {
#pragma unroll
                for (int r = 0; r < 4; r++) {
                    int m = m0 + wm * 32 + mi * 16 + g + (r >> 1) * 8;
                    int d = wn * 32 + nj * 8 + 2 * t + (r & 1);
                    int s = m & 2047;
                    out[(hb64 + d) * Sq + s] = bfbits(acc[mi][nj][r]);
                }
            }
    }
}

// fc GEMM (proven)
__global__ __launch_bounds__(256)
void gemm_fc(const uint16_t* __restrict__ Ah, const uint16_t* __restrict__ Al,
             const uint16_t* __restrict__ Bh, const uint16_t* __restrict__ Bl,
             float* __restrict__ out, const float* __restrict__ resid)
{
    extern __shared__ uint16_t sb[];
    const int tid = threadIdx.x;
    const int warp = tid >> 5, lane = tid & 31;
    const int g = lane >> 2, t = lane & 3;
    const int wm = warp >> 1, wn = warp & 1;
    const int n0 = blockIdx.x * 64;
    const int m0 = blockIdx.y * 128;

    float acc[2][4][4];
#pragma unroll
    for (int i = 0; i < 2; i++)
#pragma unroll
        for (int j = 0; j < 4; j++)
#pragma unroll
            for (int r = 0; r < 4; r++) acc[i][j][r] = 0.f;

    gemm4t_mainloop(sb, Ah, Al, Bh, Bl, m0, n0, tid, wm, wn, g, t, acc);

#pragma unroll
    for (int mi = 0; mi < 2; mi++)
#pragma unroll
        for (int nj = 0; nj < 4; nj++) {
            int n = n0 + wn * 32 + nj * 8 + 2 * t;
#pragma unroll
            for (int half = 0; half < 2; half++) {
                int m = m0 + wm * 32 + mi * 16 + g + half * 8;
                float2 rv = *(const float2*)&resid[(size_t)m * 512 + n];
                *(float2*)&out[(size_t)m * 512 + n] =
                    make_float2(acc[mi][nj][half * 2] + rv.x,
                                acc[mi][nj][half * 2 + 1] + rv.y);
            }
        }
}

// ---------------------------------------------------------------------------
// Fused attention — barrier-free per-warp pipelines (round-15 proven).
// Phase 5 now uses 3 per-warp V buffers with stage-distance 2 (wait<2>).
// ---------------------------------------------------------------------------
__global__ __launch_bounds__(512, 1)
void attn_kernel(const uint16_t* __restrict__ Qm, const uint16_t* __restrict__ Km,
                 const uint16_t* __restrict__ Vt, const unsigned* __restrict__ mask,
                 float* __restrict__ attn_out,
                 uint16_t* __restrict__ ctxh, uint16_t* __restrict__ ctxl)
{
    extern __shared__ char smc[];
    float*    scores = (float*)smc;
    uint16_t* pb     = (uint16_t*)(smc + OFF_K);
    uint16_t* qs     = (uint16_t*)smc;           // prologue only

    const int bh  = blockIdx.x;
    const int qt  = blockIdx.y;
    const int b   = bh >> 3;
    const int h   = bh & 7;
    const int tid = threadIdx.x;
    const int warp = tid >> 5;
    const int lane = tid & 31;
    const int g = lane >> 2;
    const int t = lane & 3;
    const int wg = warp >> 3;
    const int wi = warp & 7;
    const int n0 = warp * 8;
    const int d0w = wi * 8;

    const uint16_t* KB = Km + (size_t)bh * Sq * 128;
    const uint16_t* VB = Vt + (size_t)bh * 64 * Sq;

    char* kw = smc + OFF_K + warp * (2 * KWB);   // this warp's K buffers
    char* vw = smc + warp * (3 * VWB);           // this warp's V buffers (scores region)

#define STAGE_KW(buf, kt_)                                                   \
    {                                                                        \
        char* _d = kw + (buf) * KWB;                                         \
        const uint16_t* _s = KB + (size_t)((kt_) * 128 + n0) * 128;          \
        _Pragma("unroll")                                                    \
        for (int _j = 0; _j < 4; _j++) {                                     \
            int _c = lane + _j * 32;                                         \
            int _r = _c >> 4, _c16 = _c & 15;                                \
            cp16g(_d + _r * 272 + _c16 * 16, _s + _r * 128 + _c16 * 8);      \
        }                                                                    \
    }
#define STAGE_VW(buf, kt_)                                                   \
    {                                                                        \
        char* _d = vw + (buf) * VWB;                                         \
        const uint16_t* _s = VB + (size_t)d0w * Sq + (kt_) * 128 + wg * 64;  \
        _Pragma("unroll")                                                    \
        for (int _j = 0; _j < 2; _j++) {                                     \
            int _c = lane + _j * 32;                                         \
            int _r = _c >> 3, _c16 = _c & 7;                                 \
            cp16g(_d + _r * 144 + _c16 * 16, _s + (size_t)_r * Sq + _c16 * 8);\
        }                                                                    \
    }

    // prologue: per-warp K tile 0; Q (cooperative) into qs
    STAGE_KW(0, 0);
    cp_commit();
    if (tid < 256) {
        int r = tid >> 4, c16 = tid & 15;
        cp16g((char*)qs + r * 272 + c16 * 16,
              Qm + (size_t)bh * Sq * 128 + (size_t)(qt * 16 + r) * 128 + c16 * 8);
    }
    cp_commit();
    cp_wait<0>();
    __syncthreads();

    uint32_t qh[4][4], ql[4][4];
#pragma unroll
    for (int ch = 0; ch < 4; ch++) {
        int c0 = ch * 16 + 2 * t;
        qh[ch][0] = *(uint32_t*)&qs[g * 136 + c0];
        qh[ch][1] = *(uint32_t*)&qs[(g + 8) * 136 + c0];
        qh[ch][2] = *(uint32_t*)&qs[g * 136 + c0 + 8];
        qh[ch][3] = *(uint32_t*)&qs[(g + 8) * 136 + c0 + 8];
        ql[ch][0] = *(uint32_t*)&qs[g * 136 + c0 + 64];
        ql[ch][1] = *(uint32_t*)&qs[(g + 8) * 136 + c0 + 64];
        ql[ch][2] = *(uint32_t*)&qs[g * 136 + c0 + 72];
        ql[ch][3] = *(uint32_t*)&qs[(g + 8) * 136 + c0 + 72];
    }
    __syncthreads();   // qs fully consumed before any scores writes

    // ---- phase 2: scores = Q @ K^T — per-warp pipeline, no CTA barriers ----
#pragma unroll 1
    for (int kt = 0; kt < NTK; kt++) {
        if (kt + 1 < NTK) { STAGE_KW((kt + 1) & 1, kt + 1); }
        cp_commit();
        cp_wait<1>();                             // this warp's tile kt landed

        const uint16_t* kb_ = (const uint16_t*)(kw + (kt & 1) * KWB);
        float acc[2][4] = {{0.f,0.f,0.f,0.f},{0.f,0.f,0.f,0.f}};
#pragma unroll
        for (int ch = 0; ch < 4; ch++) {
            const uint16_t* kr = &kb_[g * 136 + ch * 16 + 2 * t];
            uint32_t bh0 = *(const uint32_t*)kr;
            uint32_t bh1 = *(const uint32_t*)(kr + 8);
            uint32_t bl0 = *(const uint32_t*)(kr + 64);
            uint32_t bl1 = *(const uint32_t*)(kr + 72);
            mma16(acc[ch & 1], qh[ch], bh0, bh1);
            mma16(acc[ch & 1], ql[ch], bh0, bh1);
            mma16(acc[ch & 1], qh[ch], bl0, bl1);
        }
        int col = kt * 128 + n0 + 2 * t;
        *(float2*)&scores[g * SST + col]       = make_float2(acc[0][0] + acc[1][0], acc[0][1] + acc[1][1]);
        *(float2*)&scores[(g + 8) * SST + col] = make_float2(acc[0][2] + acc[1][2], acc[0][3] + acc[1][3]);
    }
    __syncthreads();   // all scores visible; kbuf region free for pb

    // ---- phase 3/4: mask+exp+sum, normalize + attn write + bf16 P pack ----
    {
        const int row = warp;
        const int qg  = qt * 16 + row;
        const uint2* mrow2 = (const uint2*)(mask + ((size_t)b * Sq + qg) * Sq);
        float2* srow2 = (float2*)(scores + row * SST);

        float sum = 0.f;
#pragma unroll 4
        for (int i = lane; i < 1024; i += 32) {
            float2 s = srow2[i];
            uint2  m = mrow2[i];
            float px = m.x ? 0.f : __expf(s.x);
            float py = m.y ? 0.f : __expf(s.y);
            srow2[i] = make_float2(px, py);
            sum += px + py;
        }
#pragma unroll
        for (int o = 16; o; o >>= 1) sum += __shfl_xor_sync(0xffffffffu, sum, o);
        float inv = 1.0f / sum;

        uint32_t* prow = (uint32_t*)&pb[row * PBS];
        if (attn_out) {
            float2* arow2 = (float2*)(attn_out + ((size_t)bh * Sq + qg) * Sq);
#pragma unroll 4
            for (int i = lane; i < 1024; i += 32) {
                float2 p = srow2[i];
                float2 pn = make_float2(p.x * inv, p.y * inv);
                arow2[i] = pn;
                __nv_bfloat162 h2 = __float22bfloat162_rn(pn);
                prow[i] = *(uint32_t*)&h2;
            }
        } else {
#pragma unroll 4
            for (int i = lane; i < 1024; i += 32) {
                float2 p = srow2[i];
                float2 pn = make_float2(p.x * inv, p.y * inv);
                __nv_bfloat162 h2 = __float22bfloat162_rn(pn);
                prow[i] = *(uint32_t*)&h2;
            }
        }
    }
    __syncthreads();   // pb complete; scores region dead -> per-warp V buffers

    // ---- phase 5: ctx = P @ V — per-warp 3-buffer ring, distance 2 ----
    STAGE_VW(0, 0);
    cp_commit();
    STAGE_VW(1, 1);
    cp_commit();

    float cacc[2][4] = {{0.f,0.f,0.f,0.f},{0.f,0.f,0.f,0.f}};
#pragma unroll 1
    for (int kt = 0; kt < NTV; kt++) {
        if (kt + 2 < NTV) { STAGE_VW((kt + 2) % 3, kt + 2); }
        cp_commit();                              // uniform pending count
        cp_wait<2>();                             // this warp's tile kt landed

        const uint16_t* vb_ = (const uint16_t*)(vw + (kt % 3) * VWB);
        const int kb0 = kt * 128 + wg * 64;
#pragma unroll
        for (int sub = 0; sub < 4; sub++) {
            int k0 = kb0 + sub * 16;
            uint32_t a[4];
            const uint16_t* p0 = &pb[g * PBS + k0 + 2 * t];
            const uint16_t* p1 = &pb[(g + 8) * PBS + k0 + 2 * t];
            a[0] = *(const uint32_t*)p0;
            a[1] = *(const uint32_t*)p1;
            a[2] = *(const uint32_t*)(p0 + 8);
            a[3] = *(const uint32_t*)(p1 + 8);
            const uint16_t* vr = &vb_[g * 72 + sub * 16 + 2 * t];
            uint32_t b0 = *(const uint32_t*)vr;
            uint32_t b1 = *(const uint32_t*)(vr + 8);
            mma16(cacc[sub & 1], a, b0, b1);
        }
    }

    // cross-group reduction in red region (after vbufs; exact fp32)
    float2 r0 = make_float2(cacc[0][0] + cacc[1][0], cacc[0][1] + cacc[1][1]);
    float2 r1 = make_float2(cacc[0][2] + cacc[1][2], cacc[0][3] + cacc[1][3]);
    float* red = (float*)(smc + OFF_RED);
    __syncthreads();
    if (wg == 1) {
        *(float2*)&red[g * 68 + d0w + 2 * t]       = r0;
        *(float2*)&red[(g + 8) * 68 + d0w + 2 * t] = r1;
    }
    __syncthreads();
    if (wg == 0) {
        float2 p0 = *(float2*)&red[g * 68 + d0w + 2 * t];
        float2 p1 = *(float2*)&red[(g + 8) * 68 + d0w + 2 * t];
        int qg   = qt * 16;
        int dcol = h * 64 + d0w + 2 * t;
        float c00 = r0.x + p0.x, c01 = r0.y + p0.y;
        float c10 = r1.x + p1.x, c11 = r1.y + p1.y;
        size_t o0 = ((size_t)b * Sq + qg + g) * Dq + dcol;
        size_t o1 = ((size_t)b * Sq + qg + g + 8) * Dq + dcol;
        uint16_t h00 = bfbits(c00), h01 = bfbits(c01);
        uint16_t h10 = bfbits(c10), h11 = bfbits(c11);
        *(uint32_t*)&ctxh[o0] = (uint32_t)h00 | ((uint32_t)h01 << 16);
        *(uint32_t*)&ctxh[o1] = (uint32_t)h10 | ((uint32_t)h11 << 16);
        uint16_t l00 = bfbits(c00 - bf2f(h00)), l01 = bfbits(c01 - bf2f(h01));
        uint16_t l10 = bfbits(c10 - bf2f(h10)), l11 = bfbits(c11 - bf2f(h11));
        *(uint32_t*)&ctxl[o0] = (uint32_t)l00 | ((uint32_t)l01 << 16);
        *(uint32_t*)&ctxl[o1] = (uint32_t)l10 | ((uint32_t)l11 << 16);
    }
#undef STAGE_KW
#undef STAGE_VW
}

// ---------------------------------------------------------------------------
__global__ __launch_bounds__(128)
void ln_kernel(const float* __restrict__ x, const float* __restrict__ gamma,
               const float* __restrict__ beta, float* __restrict__ out)
{
    const int row = blockIdx.x;
    const int tid = threadIdx.x;
    const float* xr = x + (size_t)row * 512;

    float4 v = *(const float4*)(xr + tid * 4);
    float s  = v.x + v.y + v.z + v.w;
    float ss = v.x * v.x + v.y * v.y + v.z * v.z + v.w * v.w;

    const int lane = tid & 31, warp = tid >> 5;
#pragma unroll
    for (int o = 16; o; o >>= 1) {
        s  += __shfl_xor_sync(0xffffffffu, s, o);
        ss += __shfl_xor_sync(0xffffffffu, ss, o);
    }
    __shared__ float sh_s[4], sh_ss[4];
    if (lane == 0) { sh_s[warp] = s; sh_ss[warp] = ss; }
    __syncthreads();
    float tot  = sh_s[0] + sh_s[1] + sh_s[2] + sh_s[3];
    float tots = sh_ss[0] + sh_ss[1] + sh_ss[2] + sh_ss[3];

    float mu   = tot * (1.0f / 512.0f);
    float var  = tots * (1.0f / 512.0f) - mu * mu;
    float rstd = rsqrtf(var + LN_EPS);

    float4 g  = *(const float4*)(gamma + tid * 4);
    float4 be = *(const float4*)(beta + tid * 4);
    float4 r;
    r.x = (v.x - mu) * rstd * g.x + be.x;
    r.y = (v.y - mu) * rstd * g.y + be.y;
    r.z = (v.z - mu) * rstd * g.z + be.z;
    r.w = (v.w - mu) * rstd * g.w + be.w;
    *(float4*)&out[(size_t)row * 512 + tid * 4] = r;
}

// ---------------------------------------------------------------------------
extern "C" void kernel_launch(void* const* d_in, const int* in_sizes, int n_in,
                              void* d_out, int out_size)
{
    const float*    inQ   = (const float*)d_in[0];
    const float*    inK   = (const float*)d_in[1];
    const float*    inV   = (const float*)d_in[2];
    const unsigned* mask  = (const unsigned*)d_in[3];
    const float*    WQ    = (const float*)d_in[4];
    const float*    WK    = (const float*)d_in[5];
    const float*    WV    = (const float*)d_in[6];
    const float*    Wfc   = (const float*)d_in[7];
    const float*    gamma = (const float*)d_in[8];
    const float*    beta  = (const float*)d_in[9];
    float* out = (float*)d_out;

    uint16_t *gQ, *gK, *gV;
    uint16_t *sQh, *sQl, *sKh, *sKl, *sVh, *sVl, *sCh, *sCl;
    uint16_t *wQh, *wQl, *wKh, *wKl, *wVh, *wVl, *wFh, *wFl;
    float *gpre;
    cudaGetSymbolAddress((void**)&gQ,   g_Q);
    cudaGetSymbolAddress((void**)&gK,   g_K);
    cudaGetSymbolAddress((void**)&gV,   g_V);
    cudaGetSymbolAddress((void**)&gpre, g_pre);
    cudaGetSymbolAddress((void**)&sQh, s_Qh);  cudaGetSymbolAddress((void**)&sQl, s_Ql);
    cudaGetSymbolAddress((void**)&sKh, s_Kh);  cudaGetSymbolAddress((void**)&sKl, s_Kl);
    cudaGetSymbolAddress((void**)&sVh, s_Vh);  cudaGetSymbolAddress((void**)&sVl, s_Vl);
    cudaGetSymbolAddress((void**)&sCh, s_Ch);  cudaGetSymbolAddress((void**)&sCl, s_Cl);
    cudaGetSymbolAddress((void**)&wQh, w_Qh);  cudaGetSymbolAddress((void**)&wQl, w_Ql);
    cudaGetSymbolAddress((void**)&wKh, w_Kh);  cudaGetSymbolAddress((void**)&wKl, w_Kl);
    cudaGetSymbolAddress((void**)&wVh, w_Vh);  cudaGetSymbolAddress((void**)&wVl, w_Vl);
    cudaGetSymbolAddress((void**)&wFh, w_Fh);  cudaGetSymbolAddress((void**)&wFl, w_Fl);

    const int n4 = (Bq * Sq * Dq) / 4;
    split_in3<<<dim3((n4 + 511) / 512, 3), 512>>>(
        (const float4*)inQ, (const float4*)inK, (const float4*)inV,
        (uint2*)sQh, (uint2*)sQl, (uint2*)sKh, (uint2*)sKl,
        (uint2*)sVh, (uint2*)sVl, n4);
    splitW4<<<dim3(16, 16, 4), dim3(32, 8)>>>(WQ, WK, WV, Wfc,
        wQh, wQl, wKh, wKl, wVh, wVl, wFh, wFl);

    const int SMG = (2 * 128 * 40 + 2 * 64 * 40) * 2 * 2;   // 61,440 B
    cudaFuncSetAttribute(gemm_qkv, cudaFuncAttributeMaxDynamicSharedMemorySize, SMG);
    cudaFuncSetAttribute(gemm_fc,  cudaFuncAttributeMaxDynamicSharedMemorySize, SMG);

    gemm_qkv<<<dim3(8, 64, 3), 256, SMG>>>(
        sQh, sQl, wQh, wQl, gQ,
        sKh, sKl, wKh, wKl, gK,
        sVh, sVl, wVh, wVl, gV);

    const size_t BSD  = (size_t)Bq * Sq * Dq;
    const size_t BHSS = (size_t)Bq * Hq * Sq * Sq;
    float* attn_ptr = ((size_t)out_size >= BSD + BHSS) ? (out + BSD) : nullptr;

    cudaFuncSetAttribute(attn_kernel, cudaFuncAttributeMaxDynamicSharedMemorySize, SMEM_ATTN);
    attn_kernel<<<dim3(32, 128), 512, SMEM_ATTN>>>(gQ, gK, gV, mask, attn_ptr, sCh, sCl);

    gemm_fc<<<dim3(8, 64), 256, SMG>>>(sCh, sCl, wFh, wFl, gpre, inQ);
    ln_kernel<<<Bq * Sq, 128>>>(gpre, gamma, beta, out);
}

// round 17
// speedup vs baseline: 1.2359x; 1.0739x over previous
#include <cuda_runtime.h>
#include <cuda_bf16.h>
#include <cstdint>

// Problem constants
#define Bq   4
#define Sq   2048
#define Dq   512
#define Hq   8
#define LN_EPS 1e-5f

// attn smem layout (bytes)
#define SST        2052
#define OFF_K      (16 * SST * 4)             // 131,328 : per-warp K double-buffers / pb
#define KWB        2176                       // per-warp K buf: 8 rows x 272B
#define VWB        2304                       // per-warp V buf: 8 rows x 144B (64 keys)
#define OFF_RED    (3 * 16 * VWB)             // 110,592 : red after 3-deep vbufs
#define SMEM_ATTN  (OFF_K + 16 * 2 * KWB)     // 200,960
#define PBS        2056
#define NTK        16
#define NTV        16

// Scratch (device globals)
__device__ __align__(16) uint16_t g_Q[(size_t)Bq*Hq*Sq*128];   // bf16 [B,H,S,(hi64|lo64)]
__device__ __align__(16) uint16_t g_K[(size_t)Bq*Hq*Sq*128];
__device__ __align__(16) uint16_t g_V[(size_t)Bq*Hq*64*Sq];    // bf16 transposed [B,H,d,S]
__device__ float    g_pre[(size_t)Bq*Sq*Dq];
// bf16 hi/lo splits
__device__ __align__(16) uint16_t s_Qh[(size_t)Bq*Sq*Dq], s_Ql[(size_t)Bq*Sq*Dq];
__device__ __align__(16) uint16_t s_Kh[(size_t)Bq*Sq*Dq], s_Kl[(size_t)Bq*Sq*Dq];
__device__ __align__(16) uint16_t s_Vh[(size_t)Bq*Sq*Dq], s_Vl[(size_t)Bq*Sq*Dq];
__device__ __align__(16) uint16_t s_Ch[(size_t)Bq*Sq*Dq], s_Cl[(size_t)Bq*Sq*Dq];
__device__ __align__(16) uint16_t w_Qh[512*512], w_Ql[512*512];
__device__ __align__(16) uint16_t w_Kh[512*512], w_Kl[512*512];
__device__ __align__(16) uint16_t w_Vh[512*512], w_Vl[512*512];
__device__ __align__(16) uint16_t w_Fh[512*512], w_Fl[512*512];

// ---------------------------------------------------------------------------
__device__ __forceinline__ uint16_t bfbits(float x) {
    __nv_bfloat16 b = __float2bfloat16_rn(x);
    return *(uint16_t*)&b;
}
__device__ __forceinline__ float bf2f(uint16_t u) {
    __nv_bfloat16 b = *(__nv_bfloat16*)&u;
    return __bfloat162float(b);
}

__device__ __forceinline__ void mma16(float* c, const uint32_t* a, uint32_t b0, uint32_t b1) {
    asm volatile(
        "mma.sync.aligned.m16n8k16.row.col.f32.bf16.bf16.f32 "
        "{%0,%1,%2,%3}, {%4,%5,%6,%7}, {%8,%9}, {%0,%1,%2,%3};"
        : "+f"(c[0]), "+f"(c[1]), "+f"(c[2]), "+f"(c[3])
        : "r"(a[0]), "r"(a[1]), "r"(a[2]), "r"(a[3]), "r"(b0), "r"(b1));
}

__device__ __forceinline__ void cp16g(void* dst, const void* src) {
    uint32_t d = (uint32_t)__cvta_generic_to_shared(dst);
    asm volatile("cp.async.cg.shared.global [%0], [%1], 16;" :: "r"(d), "l"(src));
}
__device__ __forceinline__ void cp_commit() { asm volatile("cp.async.commit_group;"); }
template<int N> __device__ __forceinline__ void cp_wait() {
    asm volatile("cp.async.wait_group %0;" :: "n"(N));
}

// ---------------------------------------------------------------------------
// Split kernels (proven)
// ---------------------------------------------------------------------------
__global__ __launch_bounds__(512)
void split_in3(const float4* __restrict__ xQ, const float4* __restrict__ xK,
               const float4* __restrict__ xV,
               uint2* __restrict__ hQ, uint2* __restrict__ lQ,
               uint2* __restrict__ hK, uint2* __restrict__ lK,
               uint2* __restrict__ hV, uint2* __restrict__ lV, int n4)
{
    int i = blockIdx.x * 512 + threadIdx.x;
    if (i >= n4) return;
    const int y = blockIdx.y;
    const float4* x = (y == 0) ? xQ : (y == 1) ? xK : xV;
    uint2* hi = (y == 0) ? hQ : (y == 1) ? hK : hV;
    uint2* lo = (y == 0) ? lQ : (y == 1) ? lK : lV;
    float4 v = x[i];
    float vv[4] = {v.x, v.y, v.z, v.w};
    uint16_t h[4], l[4];
#pragma unroll
    for (int k = 0; k < 4; k++) {
        h[k] = bfbits(vv[k]);
        l[k] = bfbits(vv[k] - bf2f(h[k]));
    }
    hi[i] = *(uint2*)h;
    lo[i] = *(uint2*)l;
}

__global__ __launch_bounds__(256)
void splitW4(const float* __restrict__ W0, const float* __restrict__ W1,
             const float* __restrict__ W2, const float* __restrict__ W3,
             uint16_t* __restrict__ h0, uint16_t* __restrict__ l0,
             uint16_t* __restrict__ h1, uint16_t* __restrict__ l1,
             uint16_t* __restrict__ h2, uint16_t* __restrict__ l2,
             uint16_t* __restrict__ h3, uint16_t* __restrict__ l3)
{
    __shared__ float tile[32][33];
    const int z = blockIdx.z;
    const float* W = (z == 0) ? W0 : (z == 1) ? W1 : (z == 2) ? W2 : W3;
    uint16_t* th = (z == 0) ? h0 : (z == 1) ? h1 : (z == 2) ? h2 : h3;
    uint16_t* tl = (z == 0) ? l0 : (z == 1) ? l1 : (z == 2) ? l2 : l3;
    const int bx = blockIdx.x;
    const int by = blockIdx.y;
    const int x = threadIdx.x, y = threadIdx.y;
#pragma unroll
    for (int i = 0; i < 32; i += 8)
        tile[y + i][x] = W[(size_t)(by * 32 + y + i) * 512 + bx * 32 + x];
    __syncthreads();
#pragma unroll
    for (int i = 0; i < 32; i += 8) {
        float v = tile[x][y + i];
        uint16_t hb = bfbits(v);
        size_t o = (size_t)(bx * 32 + y + i) * 512 + by * 32 + x;
        th[o] = hb;
        tl[o] = bfbits(v - bf2f(hb));
    }
}

// ---------------------------------------------------------------------------
// PROVEN bf16 mainloop; now 3-term (use_bl=true: Ah·Bh + Al·Bh + Ah·Bl)
// or 2-term (use_bl=false: Ah·Bh + Al·Bh, Bl never staged/read).
// Structure otherwise byte-identical to the round-8..16 proven loop.
// ---------------------------------------------------------------------------
__device__ __forceinline__ void gemm4t_mainloop(
    uint16_t* sb,
    const uint16_t* __restrict__ Ah, const uint16_t* __restrict__ Al,
    const uint16_t* __restrict__ Bh, const uint16_t* __restrict__ Bl,
    int m0, int n0, int tid, int wm, int wn, int g, int t, bool use_bl,
    float acc[2][4][4])
{
    const int AU = 128 * 40, BU = 64 * 40;
    const int BUF = 2 * AU + 2 * BU;

#define QK_STAGE(buf, kk_)                                                      \
    {                                                                           \
        uint16_t* _Ash = sb + (buf) * BUF;                                      \
        uint16_t* _Asl = _Ash + AU;                                             \
        uint16_t* _Bsh = _Ash + 2 * AU;                                         \
        uint16_t* _Bsl = _Bsh + BU;                                             \
        const int _k0 = (kk_) * 32;                                             \
        _Pragma("unroll")                                                       \
        for (int _j = 0; _j < 2; _j++) {                                        \
            int _c = tid + _j * 256, _r = _c >> 2, _q = _c & 3;                 \
            cp16g(_Ash + _r * 40 + _q * 8, Ah + (size_t)(m0 + _r) * 512 + _k0 + _q * 8); \
            cp16g(_Asl + _r * 40 + _q * 8, Al + (size_t)(m0 + _r) * 512 + _k0 + _q * 8); \
        }                                                                       \
        {                                                                       \
            int _r = tid >> 2, _q = tid & 3;                                    \
            cp16g(_Bsh + _r * 40 + _q * 8, Bh + (size_t)(n0 + _r) * 512 + _k0 + _q * 8); \
            if (use_bl)                                                         \
                cp16g(_Bsl + _r * 40 + _q * 8, Bl + (size_t)(n0 + _r) * 512 + _k0 + _q * 8); \
        }                                                                       \
    }

    QK_STAGE(0, 0);
    cp_commit();

#pragma unroll 1
    for (int kk = 0; kk < 16; kk++) {
        cp_wait<0>();
        __syncthreads();
        if (kk < 15) { QK_STAGE((kk + 1) & 1, kk + 1); }
        cp_commit();

        const uint16_t* Ash = sb + (kk & 1) * BUF;
        const uint16_t* Asl = Ash + AU;
        const uint16_t* Bsh = Ash + 2 * AU;
        const uint16_t* Bsl = Bsh + BU;

#pragma unroll
        for (int kc = 0; kc < 2; kc++) {
            uint32_t ah_[2][4], al_[2][4];
#pragma unroll
            for (int mi = 0; mi < 2; mi++) {
                int base = (wm * 32 + mi * 16 + g) * 40 + kc * 16 + 2 * t;
                ah_[mi][0] = *(const uint32_t*)&Ash[base];
                ah_[mi][1] = *(const uint32_t*)&Ash[base + 320];
                ah_[mi][2] = *(const uint32_t*)&Ash[base + 8];
                ah_[mi][3] = *(const uint32_t*)&Ash[base + 328];
                al_[mi][0] = *(const uint32_t*)&Asl[base];
                al_[mi][1] = *(const uint32_t*)&Asl[base + 320];
                al_[mi][2] = *(const uint32_t*)&Asl[base + 8];
                al_[mi][3] = *(const uint32_t*)&Asl[base + 328];
            }
#pragma unroll
            for (int nj = 0; nj < 4; nj++) {
                int nb = (wn * 32 + nj * 8 + g) * 40 + kc * 16 + 2 * t;
                uint32_t bh0 = *(const uint32_t*)&Bsh[nb];
                uint32_t bh1 = *(const uint32_t*)&Bsh[nb + 8];
#pragma unroll
                for (int mi = 0; mi < 2; mi++) {
                    mma16(acc[mi][nj], ah_[mi], bh0, bh1);
                    mma16(acc[mi][nj], al_[mi], bh0, bh1);
                }
                if (use_bl) {
                    uint32_t bl0 = *(const uint32_t*)&Bsl[nb];
                    uint32_t bl1 = *(const uint32_t*)&Bsl[nb + 8];
#pragma unroll
                    for (int mi = 0; mi < 2; mi++) {
                        mma16(acc[mi][nj], ah_[mi], bl0, bl1);
                    }
                }
            }
        }
    }
#undef QK_STAGE
}

// ---------------------------------------------------------------------------
// Merged Q/K/V projection GEMM. Q/K: 3-term; V: 2-term (weights plain bf16).
// ---------------------------------------------------------------------------
__global__ __launch_bounds__(256)
void gemm_qkv(const uint16_t* __restrict__ Qh, const uint16_t* __restrict__ Ql_,
              const uint16_t* __restrict__ WQh, const uint16_t* __restrict__ WQl,
              uint16_t* __restrict__ outQ,
              const uint16_t* __restrict__ Kh, const uint16_t* __restrict__ Kl_,
              const uint16_t* __restrict__ WKh, const uint16_t* __restrict__ WKl,
              uint16_t* __restrict__ outK,
              const uint16_t* __restrict__ Vh, const uint16_t* __restrict__ Vl_,
              const uint16_t* __restrict__ WVh, const uint16_t* __restrict__ WVl,
              uint16_t* __restrict__ outV)
{
    extern __shared__ uint16_t sb[];
    const int z = blockIdx.z;
    const uint16_t* Ah = (z == 0) ? Qh : (z == 1) ? Kh : Vh;
    const uint16_t* Al = (z == 0) ? Ql_ : (z == 1) ? Kl_ : Vl_;
    const uint16_t* Bh = (z == 0) ? WQh : (z == 1) ? WKh : WVh;
    const uint16_t* Bl = (z == 0) ? WQl : (z == 1) ? WKl : WVl;
    uint16_t* out      = (z == 0) ? outQ : (z == 1) ? outK : outV;
    const float scale  = (z == 0) ? 0.125f : 1.0f;
    const bool use_bl  = (z < 2);

    const int tid = threadIdx.x;
    const int warp = tid >> 5, lane = tid & 31;
    const int g = lane >> 2, t = lane & 3;
    const int wm = warp >> 1, wn = warp & 1;
    const int h  = blockIdx.x;
    const int n0 = h * 64;
    const int m0 = blockIdx.y * 128;

    float acc[2][4][4];
#pragma unroll
    for (int i = 0; i < 2; i++)
#pragma unroll
        for (int j = 0; j < 4; j++)
#pragma unroll
            for (int r = 0; r < 4; r++) acc[i][j][r] = 0.f;

    gemm4t_mainloop(sb, Ah, Al, Bh, Bl, m0, n0, tid, wm, wn, g, t, use_bl, acc);

    if (z < 2) {
#pragma unroll
        for (int mi = 0; mi < 2; mi++)
#pragma unroll
            for (int nj = 0; nj < 4; nj++) {
                int e = wn * 32 + nj * 8 + 2 * t;
#pragma unroll
                for (int half = 0; half < 2; half++) {
                    int m = m0 + wm * 32 + mi * 16 + g + half * 8;
                    int b = m >> 11, s = m & 2047;
                    size_t base = (((size_t)b * Hq + h) * Sq + s) * 128 + e;
                    float v0 = acc[mi][nj][half * 2]     * scale;
                    float v1 = acc[mi][nj][half * 2 + 1] * scale;
                    uint16_t h0 = bfbits(v0), h1 = bfbits(v1);
                    uint16_t l0 = bfbits(v0 - bf2f(h0)), l1 = bfbits(v1 - bf2f(h1));
                    *(uint32_t*)(out + base)      = (uint32_t)h0 | ((uint32_t)h1 << 16);
                    *(uint32_t*)(out + base + 64) = (uint32_t)l0 | ((uint32_t)l1 << 16);
                }
            }
    } else {
        const int b  = m0 >> 11;
        const size_t hb64 = (size_t)(b * Hq + h) * 64;
#pragma unroll
        for (int mi = 0; mi < 2; mi++)
#pragma unroll
            for (int nj = 0; nj < 4; nj++) {
#pragma unroll
                for (int r = 0; r < 4; r++) {
                    int m = m0 + wm * 32 + mi * 16 + g + (r >> 1) * 8;
                    int d = wn * 32 + nj * 8 + 2 * t + (r & 1);
                    int s = m & 2047;
                    out[(hb64 + d) * Sq + s] = bfbits(acc[mi][nj][r]);
                }
            }
    }
}

// fc GEMM: 2-term (weights plain bf16)
__global__ __launch_bounds__(256)
void gemm_fc(const uint16_t* __restrict__ Ah, const uint16_t* __restrict__ Al,
             const uint16_t* __restrict__ Bh,
             float* __restrict__ out, const float* __restrict__ resid)
{
    extern __shared__ uint16_t sb[];
    const int tid = threadIdx.x;
    const int warp = tid >> 5, lane = tid & 31;
    const int g = lane >> 2, t = lane & 3;
    const int wm = warp >> 1, wn = warp & 1;
    const int n0 = blockIdx.x * 64;
    const int m0 = blockIdx.y * 128;

    float acc[2][4][4];
#pragma unroll
    for (int i = 0; i < 2; i++)
#pragma unroll
        for (int j = 0; j < 4; j++)
#pragma unroll
            for (int r = 0; r < 4; r++) acc[i][j][r] = 0.f;

    gemm4t_mainloop(sb, Ah, Al, Bh, Bh, m0, n0, tid, wm, wn, g, t, false, acc);

#pragma unroll
    for (int mi = 0; mi < 2; mi++)
#pragma unroll
        for (int nj = 0; nj < 4; nj++) {
            int n = n0 + wn * 32 + nj * 8 + 2 * t;
#pragma unroll
            for (int half = 0; half < 2; half++) {
                int m = m0 + wm * 32 + mi * 16 + g + half * 8;
                float2 rv = *(const float2*)&resid[(size_t)m * 512 + n];
                *(float2*)&out[(size_t)m * 512 + n] =
                    make_float2(acc[mi][nj][half * 2] + rv.x,
                                acc[mi][nj][half * 2 + 1] + rv.y);
            }
        }
}

// ---------------------------------------------------------------------------
// Fused attention — round-16 PROVEN version verbatim.
// ---------------------------------------------------------------------------
__global__ __launch_bounds__(512, 1)
void attn_kernel(const uint16_t* __restrict__ Qm, const uint16_t* __restrict__ Km,
                 const uint16_t* __restrict__ Vt, const unsigned* __restrict__ mask,
                 float* __restrict__ attn_out,
                 uint16_t* __restrict__ ctxh, uint16_t* __restrict__ ctxl)
{
    extern __shared__ char smc[];
    float*    scores = (float*)smc;
    uint16_t* pb     = (uint16_t*)(smc + OFF_K);
    uint16_t* qs     = (uint16_t*)smc;           // prologue only

    const int bh  = blockIdx.x;
    const int qt  = blockIdx.y;
    const int b   = bh >> 3;
    const int h   = bh & 7;
    const int tid = threadIdx.x;
    const int warp = tid >> 5;
    const int lane = tid & 31;
    const int g = lane >> 2;
    const int t = lane & 3;
    const int wg = warp >> 3;
    const int wi = warp & 7;
    const int n0 = warp * 8;
    const int d0w = wi * 8;

    const uint16_t* KB = Km + (size_t)bh * Sq * 128;
    const uint16_t* VB = Vt + (size_t)bh * 64 * Sq;

    char* kw = smc + OFF_K + warp * (2 * KWB);
    char* vw = smc + warp * (3 * VWB);

#define STAGE_KW(buf, kt_)                                                   \
    {                                                                        \
        char* _d = kw + (buf) * KWB;                                         \
        const uint16_t* _s = KB + (size_t)((kt_) * 128 + n0) * 128;          \
        _Pragma("unroll")                                                    \
        for (int _j = 0; _j < 4; _j++) {                                     \
            int _c = lane + _j * 32;                                         \
            int _r = _c >> 4, _c16 = _c & 15;                                \
            cp16g(_d + _r * 272 + _c16 * 16, _s + _r * 128 + _c16 * 8);      \
        }                                                                    \
    }
#define STAGE_VW(buf, kt_)                                                   \
    {                                                                        \
        char* _d = vw + (buf) * VWB;                                         \
        const uint16_t* _s = VB + (size_t)d0w * Sq + (kt_) * 128 + wg * 64;  \
        _Pragma("unroll")                                                    \
        for (int _j = 0; _j < 2; _j++) {                                     \
            int _c = lane + _j * 32;                                         \
            int _r = _c >> 3, _c16 = _c & 7;                                 \
            cp16g(_d + _r * 144 + _c16 * 16, _s + (size_t)_r * Sq + _c16 * 8);\
        }                                                                    \
    }

    STAGE_KW(0, 0);
    cp_commit();
    if (tid < 256) {
        int r = tid >> 4, c16 = tid & 15;
        cp16g((char*)qs + r * 272 + c16 * 16,
              Qm + (size_t)bh * Sq * 128 + (size_t)(qt * 16 + r) * 128 + c16 * 8);
    }
    cp_commit();
    cp_wait<0>();
    __syncthreads();

    uint32_t qh[4][4], ql[4][4];
#pragma unroll
    for (int ch = 0; ch < 4; ch++) {
        int c0 = ch * 16 + 2 * t;
        qh[ch][0] = *(uint32_t*)&qs[g * 136 + c0];
        qh[ch][1] = *(uint32_t*)&qs[(g + 8) * 136 + c0];
        qh[ch][2] = *(uint32_t*)&qs[g * 136 + c0 + 8];
        qh[ch][3] = *(uint32_t*)&qs[(g + 8) * 136 + c0 + 8];
        ql[ch][0] = *(uint32_t*)&qs[g * 136 + c0 + 64];
        ql[ch][1] = *(uint32_t*)&qs[(g + 8) * 136 + c0 + 64];
        ql[ch][2] = *(uint32_t*)&qs[g * 136 + c0 + 72];
        ql[ch][3] = *(uint32_t*)&qs[(g + 8) * 136 + c0 + 72];
    }
    __syncthreads();

    // ---- phase 2: per-warp pipeline ----
#pragma unroll 1
    for (int kt = 0; kt < NTK; kt++) {
        if (kt + 1 < NTK) { STAGE_KW((kt + 1) & 1, kt + 1); }
        cp_commit();
        cp_wait<1>();

        const uint16_t* kb_ = (const uint16_t*)(kw + (kt & 1) * KWB);
        float acc[2][4] = {{0.f,0.f,0.f,0.f},{0.f,0.f,0.f,0.f}};
#pragma unroll
        for (int ch = 0; ch < 4; ch++) {
            const uint16_t* kr = &kb_[g * 136 + ch * 16 + 2 * t];
            uint32_t bh0 = *(const uint32_t*)kr;
            uint32_t bh1 = *(const uint32_t*)(kr + 8);
            uint32_t bl0 = *(const uint32_t*)(kr + 64);
            uint32_t bl1 = *(const uint32_t*)(kr + 72);
            mma16(acc[ch & 1], qh[ch], bh0, bh1);
            mma16(acc[ch & 1], ql[ch], bh0, bh1);
            mma16(acc[ch & 1], qh[ch], bl0, bl1);
        }
        int col = kt * 128 + n0 + 2 * t;
        *(float2*)&scores[g * SST + col]       = make_float2(acc[0][0] + acc[1][0], acc[0][1] + acc[1][1]);
        *(float2*)&scores[(g + 8) * SST + col] = make_float2(acc[0][2] + acc[1][2], acc[0][3] + acc[1][3]);
    }
    __syncthreads();

    // ---- phase 3/4 ----
    {
        const int row = warp;
        const int qg  = qt * 16 + row;
        const uint2* mrow2 = (const uint2*)(mask + ((size_t)b * Sq + qg) * Sq);
        float2* srow2 = (float2*)(scores + row * SST);

        float sum = 0.f;
#pragma unroll 4
        for (int i = lane; i < 1024; i += 32) {
            float2 s = srow2[i];
            uint2  m = mrow2[i];
            float px = m.x ? 0.f : __expf(s.x);
            float py = m.y ? 0.f : __expf(s.y);
            srow2[i] = make_float2(px, py);
            sum += px + py;
        }
#pragma unroll
        for (int o = 16; o; o >>= 1) sum += __shfl_xor_sync(0xffffffffu, sum, o);
        float inv = 1.0f / sum;

        uint32_t* prow = (uint32_t*)&pb[row * PBS];
        if (attn_out) {
            float2* arow2 = (float2*)(attn_out + ((size_t)bh * Sq + qg) * Sq);
#pragma unroll 4
            for (int i = lane; i < 1024; i += 32) {
                float2 p = srow2[i];
                float2 pn = make_float2(p.x * inv, p.y * inv);
                arow2[i] = pn;
                __nv_bfloat162 h2 = __float22bfloat162_rn(pn);
                prow[i] = *(uint32_t*)&h2;
            }
        } else {
#pragma unroll 4
            for (int i = lane; i < 1024; i += 32) {
                float2 p = srow2[i];
                float2 pn = make_float2(p.x * inv, p.y * inv);
                __nv_bfloat162 h2 = __float22bfloat162_rn(pn);
                prow[i] = *(uint32_t*)&h2;
            }
        }
    }
    __syncthreads();

    // ---- phase 5: per-warp 3-buffer ring, distance 2 ----
    STAGE_VW(0, 0);
    cp_commit();
    STAGE_VW(1, 1);
    cp_commit();

    float cacc[2][4] = {{0.f,0.f,0.f,0.f},{0.f,0.f,0.f,0.f}};
#pragma unroll 1
    for (int kt = 0; kt < NTV; kt++) {
        if (kt + 2 < NTV) { STAGE_VW((kt + 2) % 3, kt + 2); }
        cp_commit();
        cp_wait<2>();

        const uint16_t* vb_ = (const uint16_t*)(vw + (kt % 3) * VWB);
        const int kb0 = kt * 128 + wg * 64;
#pragma unroll
        for (int sub = 0; sub < 4; sub++) {
            int k0 = kb0 + sub * 16;
            uint32_t a[4];
            const uint16_t* p0 = &pb[g * PBS + k0 + 2 * t];
            const uint16_t* p1 = &pb[(g + 8) * PBS + k0 + 2 * t];
            a[0] = *(const uint32_t*)p0;
            a[1] = *(const uint32_t*)p1;
            a[2] = *(const uint32_t*)(p0 + 8);
            a[3] = *(const uint32_t*)(p1 + 8);
            const uint16_t* vr = &vb_[g * 72 + sub * 16 + 2 * t];
            uint32_t b0 = *(const uint32_t*)vr;
            uint32_t b1 = *(const uint32_t*)(vr + 8);
            mma16(cacc[sub & 1], a, b0, b1);
        }
    }

    float2 r0 = make_float2(cacc[0][0] + cacc[1][0], cacc[0][1] + cacc[1][1]);
    float2 r1 = make_float2(cacc[0][2] + cacc[1][2], cacc[0][3] + cacc[1][3]);
    float* red = (float*)(smc + OFF_RED);
    __syncthreads();
    if (wg == 1) {
        *(float2*)&red[g * 68 + d0w + 2 * t]       = r0;
        *(float2*)&red[(g + 8) * 68 + d0w + 2 * t] = r1;
    }
    __syncthreads();
    if (wg == 0) {
        float2 p0 = *(float2*)&red[g * 68 + d0w + 2 * t];
        float2 p1 = *(float2*)&red[(g + 8) * 68 + d0w + 2 * t];
        int qg   = qt * 16;
        int dcol = h * 64 + d0w + 2 * t;
        float c00 = r0.x + p0.x, c01 = r0.y + p0.y;
        float c10 = r1.x + p1.x, c11 = r1.y + p1.y;
        size_t o0 = ((size_t)b * Sq + qg + g) * Dq + dcol;
        size_t o1 = ((size_t)b * Sq + qg + g + 8) * Dq + dcol;
        uint16_t h00 = bfbits(c00), h01 = bfbits(c01);
        uint16_t h10 = bfbits(c10), h11 = bfbits(c11);
        *(uint32_t*)&ctxh[o0] = (uint32_t)h00 | ((uint32_t)h01 << 16);
        *(uint32_t*)&ctxh[o1] = (uint32_t)h10 | ((uint32_t)h11 << 16);
        uint16_t l00 = bfbits(c00 - bf2f(h00)), l01 = bfbits(c01 - bf2f(h01));
        uint16_t l10 = bfbits(c10 - bf2f(h10)), l11 = bfbits(c11 - bf2f(h11));
        *(uint32_t*)&ctxl[o0] = (uint32_t)l00 | ((uint32_t)l01 << 16);
        *(uint32_t*)&ctxl[o1] = (uint32_t)l10 | ((uint32_t)l11 << 16);
    }
#undef STAGE_KW
#undef STAGE_VW
}

// ---------------------------------------------------------------------------
__global__ __launch_bounds__(128)
void ln_kernel(const float* __restrict__ x, const float* __restrict__ gamma,
               const float* __restrict__ beta, float* __restrict__ out)
{
    const int row = blockIdx.x;
    const int tid = threadIdx.x;
    const float* xr = x + (size_t)row * 512;

    float4 v = *(const float4*)(xr + tid * 4);
    float s  = v.x + v.y + v.z + v.w;
    float ss = v.x * v.x + v.y * v.y + v.z * v.z + v.w * v.w;

    const int lane = tid & 31, warp = tid >> 5;
#pragma unroll
    for (int o = 16; o; o >>= 1) {
        s  += __shfl_xor_sync(0xffffffffu, s, o);
        ss += __shfl_xor_sync(0xffffffffu, ss, o);
    }
    __shared__ float sh_s[4], sh_ss[4];
    if (lane == 0) { sh_s[warp] = s; sh_ss[warp] = ss; }
    __syncthreads();
    float tot  = sh_s[0] + sh_s[1] + sh_s[2] + sh_s[3];
    float tots = sh_ss[0] + sh_ss[1] + sh_ss[2] + sh_ss[3];

    float mu   = tot * (1.0f / 512.0f);
    float var  = tots * (1.0f / 512.0f) - mu * mu;
    float rstd = rsqrtf(var + LN_EPS);

    float4 g  = *(const float4*)(gamma + tid * 4);
    float4 be = *(const float4*)(beta + tid * 4);
    float4 r;
    r.x = (v.x - mu) * rstd * g.x + be.x;
    r.y = (v.y - mu) * rstd * g.y + be.y;
    r.z = (v.z - mu) * rstd * g.z + be.z;
    r.w = (v.w - mu) * rstd * g.w + be.w;
    *(float4*)&out[(size_t)row * 512 + tid * 4] = r;
}

// ---------------------------------------------------------------------------
extern "C" void kernel_launch(void* const* d_in, const int* in_sizes, int n_in,
                              void* d_out, int out_size)
{
    const float*    inQ   = (const float*)d_in[0];
    const float*    inK   = (const float*)d_in[1];
    const float*    inV   = (const float*)d_in[2];
    const unsigned* mask  = (const unsigned*)d_in[3];
    const float*    WQ    = (const float*)d_in[4];
    const float*    WK    = (const float*)d_in[5];
    const float*    WV    = (const float*)d_in[6];
    const float*    Wfc   = (const float*)d_in[7];
    const float*    gamma = (const float*)d_in[8];
    const float*    beta  = (const float*)d_in[9];
    float* out = (float*)d_out;

    uint16_t *gQ, *gK, *gV;
    uint16_t *sQh, *sQl, *sKh, *sKl, *sVh, *sVl, *sCh, *sCl;
    uint16_t *wQh, *wQl, *wKh, *wKl, *wVh, *wVl, *wFh, *wFl;
    float *gpre;
    cudaGetSymbolAddress((void**)&gQ,   g_Q);
    cudaGetSymbolAddress((void**)&gK,   g_K);
    cudaGetSymbolAddress((void**)&gV,   g_V);
    cudaGetSymbolAddress((void**)&gpre, g_pre);
    cudaGetSymbolAddress((void**)&sQh, s_Qh);  cudaGetSymbolAddress((void**)&sQl, s_Ql);
    cudaGetSymbolAddress((void**)&sKh, s_Kh);  cudaGetSymbolAddress((void**)&sKl, s_Kl);
    cudaGetSymbolAddress((void**)&sVh, s_Vh);  cudaGetSymbolAddress((void**)&sVl, s_Vl);
    cudaGetSymbolAddress((void**)&sCh, s_Ch);  cudaGetSymbolAddress((void**)&sCl, s_Cl);
    cudaGetSymbolAddress((void**)&wQh, w_Qh);  cudaGetSymbolAddress((void**)&wQl, w_Ql);
    cudaGetSymbolAddress((void**)&wKh, w_Kh);  cudaGetSymbolAddress((void**)&wKl, w_Kl);
    cudaGetSymbolAddress((void**)&wVh, w_Vh);  cudaGetSymbolAddress((void**)&wVl, w_Vl);
    cudaGetSymbolAddress((void**)&wFh, w_Fh);  cudaGetSymbolAddress((void**)&wFl, w_Fl);

    const int n4 = (Bq * Sq * Dq) / 4;
    split_in3<<<dim3((n4 + 511) / 512, 3), 512>>>(
        (const float4*)inQ, (const float4*)inK, (const float4*)inV,
        (uint2*)sQh, (uint2*)sQl, (uint2*)sKh, (uint2*)sKl,
        (uint2*)sVh, (uint2*)sVl, n4);
    splitW4<<<dim3(16, 16, 4), dim3(32, 8)>>>(WQ, WK, WV, Wfc,
        wQh, wQl, wKh, wKl, wVh, wVl, wFh, wFl);

    const int SMG = (2 * 128 * 40 + 2 * 64 * 40) * 2 * 2;   // 61,440 B
    cudaFuncSetAttribute(gemm_qkv, cudaFuncAttributeMaxDynamicSharedMemorySize, SMG);
    cudaFuncSetAttribute(gemm_fc,  cudaFuncAttributeMaxDynamicSharedMemorySize, SMG);

    gemm_qkv<<<dim3(8, 64, 3), 256, SMG>>>(
        sQh, sQl, wQh, wQl, gQ,
        sKh, sKl, wKh, wKl, gK,
        sVh, sVl, wVh, wVl, gV);

    const size_t BSD  = (size_t)Bq * Sq * Dq;
    const size_t BHSS = (size_t)Bq * Hq * Sq * Sq;
    float* attn_ptr = ((size_t)out_size >= BSD + BHSS) ? (out + BSD) : nullptr;

    cudaFuncSetAttribute(attn_kernel, cudaFuncAttributeMaxDynamicSharedMemorySize, SMEM_ATTN);
    attn_kernel<<<dim3(32, 128), 512, SMEM_ATTN>>>(gQ, gK, gV, mask, attn_ptr, sCh, sCl);

    gemm_fc<<<dim3(8, 64), 256, SMG>>>(sCh, sCl, wFh, gpre, inQ);
    ln_kernel<<<Bq * Sq, 128>>>(gpre, gamma, beta, out);
}